// round 3
// baseline (speedup 1.0000x reference)
#include <cuda_runtime.h>
#include <math.h>

#define BB   8
#define SS   1024
#define DDIM 768
#define HH   8
#define DKK  96
#define FFD  1024
#define BHN  (BB*HH)    // 64
#define MROWS (BB*SS)   // 8192

// ---------------- scratch (device globals: allocation-free rule) ------------
__device__ float g_q [MROWS*DDIM];
__device__ float g_kv[MROWS*DDIM];
__device__ float g_w [BHN*SS*SS];      // 256 MB score tensor
__device__ float g_cm[BHN*SS];         // per-column max
__device__ float g_ci[BHN*SS];         // per-column 1/sum
__device__ float g_t0[MROWS*DDIM];     // pre-LN buffer
__device__ float g_x1[MROWS*DDIM];     // layer1 out
__device__ float g_x2[MROWS*DDIM];     // layer2 out
__device__ float g_h [MROWS*FFD];      // FFN hidden
__device__ int   g_mask_u8;            // 1 if attention_mask is byte-packed

// ---------------- mask dtype probe -----------------------------------------
// bool serialized as uint8: random nonzero bytes at idx%4!=0.
// bool serialized as int32 (0/1): bytes at idx%4!=0 are always 0.
// Reads only first 8192 bytes (safe under both layouts).
__global__ void probe_mask_k(const unsigned char* __restrict__ p) {
    __shared__ int any;
    if (threadIdx.x == 0) any = 0;
    __syncthreads();
    int local = 0;
    for (int i = threadIdx.x; i < BB*SS; i += 256)
        if ((i & 3) && p[i]) local = 1;
    if (local) atomicOr(&any, 1);
    __syncthreads();
    if (threadIdx.x == 0) g_mask_u8 = any;
}

// ---------------- generic tiled GEMM: C = A[M,K] @ B[K,N] + bias ------------
// BM=64, BN=64, BK=16, 256 threads, 4x4 per thread
template<bool RELU>
__global__ void gemm_bias_k(const float* __restrict__ A, int lda,
                            const float* __restrict__ Bm, int ldb,
                            const float* __restrict__ bias,
                            float* __restrict__ C, int ldc, int K)
{
    __shared__ float As[16][68];
    __shared__ float Bs[16][68];
    const int m0 = blockIdx.y * 64;
    const int n0 = blockIdx.x * 64;
    const int tid = threadIdx.x;
    const int tx = tid & 15, ty = tid >> 4;
    float acc[4][4] = {};

    for (int k0 = 0; k0 < K; k0 += 16) {
        #pragma unroll
        for (int i = 0; i < 4; i++) {
            int idx = tid + i * 256;
            int kk = idx & 15, m = idx >> 4;
            As[kk][m] = A[(size_t)(m0 + m) * lda + k0 + kk];
        }
        #pragma unroll
        for (int i = 0; i < 4; i++) {
            int idx = tid + i * 256;
            int n = idx & 63, kk = idx >> 6;
            Bs[kk][n] = Bm[(size_t)(k0 + kk) * ldb + n0 + n];
        }
        __syncthreads();
        #pragma unroll
        for (int kk = 0; kk < 16; kk++) {
            float ra[4], rb[4];
            #pragma unroll
            for (int i = 0; i < 4; i++) ra[i] = As[kk][ty * 4 + i];
            #pragma unroll
            for (int j = 0; j < 4; j++) rb[j] = Bs[kk][tx * 4 + j];
            #pragma unroll
            for (int i = 0; i < 4; i++)
                #pragma unroll
                for (int j = 0; j < 4; j++)
                    acc[i][j] += ra[i] * rb[j];
        }
        __syncthreads();
    }
    #pragma unroll
    for (int i = 0; i < 4; i++) {
        int m = m0 + ty * 4 + i;
        #pragma unroll
        for (int j = 0; j < 4; j++) {
            int n = n0 + tx * 4 + j;
            float v = acc[i][j] + bias[n];
            if (RELU) v = fmaxf(v, 0.0f);
            C[(size_t)m * ldc + n] = v;
        }
    }
}

// ---------------- attention scores: w[bh,q,k] = <q_row, k_row>/sqrt(DK), masked
__global__ void attn_scores_k(const float* __restrict__ q,
                              const float* __restrict__ kv,
                              const void* __restrict__ pmask,
                              float* __restrict__ w)
{
    __shared__ float As[16][68];
    __shared__ float Bs[16][68];
    const int bh = blockIdx.z, b = bh >> 3, h = bh & 7;
    const float* Ap = q  + (size_t)b * SS * DDIM + h * DKK;
    const float* Bp = kv + (size_t)b * SS * DDIM + h * DKK;
    const int m0 = blockIdx.y * 64;   // q tile
    const int n0 = blockIdx.x * 64;   // k tile
    const int tid = threadIdx.x;
    const int tx = tid & 15, ty = tid >> 4;
    float acc[4][4] = {};

    for (int k0 = 0; k0 < DKK; k0 += 16) {
        #pragma unroll
        for (int i = 0; i < 4; i++) {
            int idx = tid + i * 256;
            int kk = idx & 15, m = idx >> 4;
            As[kk][m] = Ap[(size_t)(m0 + m) * DDIM + k0 + kk];
            Bs[kk][m] = Bp[(size_t)(n0 + m) * DDIM + k0 + kk];
        }
        __syncthreads();
        #pragma unroll
        for (int kk = 0; kk < 16; kk++) {
            float ra[4], rb[4];
            #pragma unroll
            for (int i = 0; i < 4; i++) ra[i] = As[kk][ty * 4 + i];
            #pragma unroll
            for (int j = 0; j < 4; j++) rb[j] = Bs[kk][tx * 4 + j];
            #pragma unroll
            for (int i = 0; i < 4; i++)
                #pragma unroll
                for (int j = 0; j < 4; j++)
                    acc[i][j] += ra[i] * rb[j];
        }
        __syncthreads();
    }

    const float scale = 0.10206207261596575f;   // 1/sqrt(96)
    const unsigned char* m8  = (const unsigned char*)pmask;
    const int*           m32 = (const int*)pmask;
    const int u8 = g_mask_u8;
    float* wo = w + (size_t)bh * SS * SS;
    #pragma unroll
    for (int i = 0; i < 4; i++) {
        int qr = m0 + ty * 4 + i;
        int padq = u8 ? (int)m8[b * SS + qr] : m32[b * SS + qr];
        #pragma unroll
        for (int j = 0; j < 4; j++) {
            int kc = n0 + tx * 4 + j;
            bool mk = (kc > qr) || (padq != 0);
            wo[(size_t)qr * SS + kc] = mk ? -1000000000.0f : acc[i][j] * scale;
        }
    }
}

// ---------------- online column softmax stats (softmax over q axis!) --------
__global__ void col_softmax_k(const float* __restrict__ w,
                              float* __restrict__ cm, float* __restrict__ ci)
{
    const int bh = blockIdx.y;
    const int k  = blockIdx.x * 256 + threadIdx.x;
    const float* wc = w + (size_t)bh * SS * SS + k;
    float m = -1e30f, s = 0.0f;
    for (int q = 0; q < SS; q++) {
        float v = wc[(size_t)q * SS];
        if (v > m) { s = s * expf(m - v) + 1.0f; m = v; }
        else       { s += expf(v - m); }
    }
    cm[bh * SS + k] = m;
    ci[bh * SS + k] = 1.0f / s;
}

// ---------------- o = softmax(w) @ v ; exp applied during A-tile load -------
// BM=64 (q), BN=96 (=DK, full width -> each w element exp'd once), BK=16
__global__ void attn_out_k(const float* __restrict__ w,
                           const float* __restrict__ kv,
                           const float* __restrict__ cm,
                           const float* __restrict__ ci,
                           float* __restrict__ o)
{
    __shared__ float As[16][68];
    __shared__ float Bs[16][100];
    const int bh = blockIdx.y, b = bh >> 3, h = bh & 7;
    const float* Ap  = w  + (size_t)bh * SS * SS;
    const float* Bp  = kv + (size_t)b * SS * DDIM + h * DKK;
    const float* cmp = cm + bh * SS;
    const float* cip = ci + bh * SS;
    const int m0 = blockIdx.x * 64;
    const int tid = threadIdx.x;
    const int tx = tid & 15, ty = tid >> 4;
    float acc[4][6] = {};

    for (int k0 = 0; k0 < SS; k0 += 16) {
        #pragma unroll
        for (int i = 0; i < 4; i++) {
            int idx = tid + i * 256;
            int kk = idx & 15, m = idx >> 4;
            float raw = Ap[(size_t)(m0 + m) * SS + k0 + kk];
            As[kk][m] = expf(raw - cmp[k0 + kk]) * cip[k0 + kk];
        }
        #pragma unroll
        for (int i = 0; i < 6; i++) {
            int idx = tid + i * 256;
            int n = idx % 96, kk = idx / 96;
            Bs[kk][n] = Bp[(size_t)(k0 + kk) * DDIM + n];
        }
        __syncthreads();
        #pragma unroll
        for (int kk = 0; kk < 16; kk++) {
            float ra[4], rb[6];
            #pragma unroll
            for (int i = 0; i < 4; i++) ra[i] = As[kk][ty * 4 + i];
            #pragma unroll
            for (int j = 0; j < 6; j++) rb[j] = Bs[kk][tx * 6 + j];
            #pragma unroll
            for (int i = 0; i < 4; i++)
                #pragma unroll
                for (int j = 0; j < 6; j++)
                    acc[i][j] += ra[i] * rb[j];
        }
        __syncthreads();
    }
    #pragma unroll
    for (int i = 0; i < 4; i++) {
        int qr = m0 + ty * 4 + i;
        float* orow = o + (size_t)(b * SS + qr) * DDIM + h * DKK;
        #pragma unroll
        for (int j = 0; j < 6; j++)
            orow[tx * 6 + j] = acc[i][j];
    }
}

// ---------------- fused residual + LayerNorm --------------------------------
__global__ void add_ln_k(const float* __restrict__ o, const float* __restrict__ x,
                         const float* __restrict__ g, const float* __restrict__ bta,
                         float* __restrict__ out)
{
    __shared__ float red[256];
    const int row = blockIdx.x;
    const int tid = threadIdx.x;
    const float* op = o + (size_t)row * DDIM;
    const float* xp = x + (size_t)row * DDIM;
    float v[3];
    float lsum = 0.0f;
    #pragma unroll
    for (int i = 0; i < 3; i++) {
        int c = tid + i * 256;
        v[i] = op[c] + xp[c];
        lsum += v[i];
    }
    red[tid] = lsum; __syncthreads();
    for (int st = 128; st > 0; st >>= 1) {
        if (tid < st) red[tid] += red[tid + st];
        __syncthreads();
    }
    float mean = red[0] * (1.0f / 768.0f);
    __syncthreads();
    float lsq = 0.0f;
    #pragma unroll
    for (int i = 0; i < 3; i++) { float d = v[i] - mean; lsq += d * d; }
    red[tid] = lsq; __syncthreads();
    for (int st = 128; st > 0; st >>= 1) {
        if (tid < st) red[tid] += red[tid + st];
        __syncthreads();
    }
    float inv = rsqrtf(red[0] * (1.0f / 768.0f) + 1e-5f);
    #pragma unroll
    for (int i = 0; i < 3; i++) {
        int c = tid + i * 256;
        out[(size_t)row * DDIM + c] = (v[i] - mean) * inv * g[c] + bta[c];
    }
}

// ---------------- launch -----------------------------------------------------
extern "C" void kernel_launch(void* const* d_in, const int* in_sizes, int n_in,
                              void* d_out, int out_size)
{
    const float* x     = (const float*)d_in[0];
    const void*  amask = d_in[1];
    const float* a1_Wq = (const float*)d_in[2],  *a1_bq = (const float*)d_in[3];
    const float* a1_Wv = (const float*)d_in[4],  *a1_bv = (const float*)d_in[5];
    const float* a1_g  = (const float*)d_in[6],  *a1_b  = (const float*)d_in[7];
    const float* a2_Wq = (const float*)d_in[8],  *a2_bq = (const float*)d_in[9];
    const float* a2_Wv = (const float*)d_in[10], *a2_bv = (const float*)d_in[11];
    const float* a2_g  = (const float*)d_in[12], *a2_b  = (const float*)d_in[13];
    const float* f_W1  = (const float*)d_in[14], *f_b1  = (const float*)d_in[15];
    const float* f_W2  = (const float*)d_in[16], *f_b2  = (const float*)d_in[17];
    const float* f_g   = (const float*)d_in[18], *f_b   = (const float*)d_in[19];
    float* out = (float*)d_out;

    float *p_q, *p_kv, *p_w, *p_cm, *p_ci, *p_t0, *p_x1, *p_x2, *p_h;
    cudaGetSymbolAddress((void**)&p_q,  g_q);
    cudaGetSymbolAddress((void**)&p_kv, g_kv);
    cudaGetSymbolAddress((void**)&p_w,  g_w);
    cudaGetSymbolAddress((void**)&p_cm, g_cm);
    cudaGetSymbolAddress((void**)&p_ci, g_ci);
    cudaGetSymbolAddress((void**)&p_t0, g_t0);
    cudaGetSymbolAddress((void**)&p_x1, g_x1);
    cudaGetSymbolAddress((void**)&p_x2, g_x2);
    cudaGetSymbolAddress((void**)&p_h,  g_h);

    probe_mask_k<<<1, 256>>>((const unsigned char*)amask);

    const dim3 gProj(12, 128);           // N=768, M=8192
    const dim3 gScore(16, 16, 64);       // k-tiles, q-tiles, bh
    const dim3 gSoft(4, 64);
    const dim3 gAO(16, 64);              // q-tiles, bh
    const dim3 gF1(16, 128);             // N=1024

    // ---- MHA layer 1 ----
    gemm_bias_k<false><<<gProj, 256>>>(x, DDIM, a1_Wq, DDIM, a1_bq, p_q,  DDIM, DDIM);
    gemm_bias_k<false><<<gProj, 256>>>(x, DDIM, a1_Wv, DDIM, a1_bv, p_kv, DDIM, DDIM);
    attn_scores_k<<<gScore, 256>>>(p_q, p_kv, amask, p_w);
    col_softmax_k<<<gSoft, 256>>>(p_w, p_cm, p_ci);
    attn_out_k<<<gAO, 256>>>(p_w, p_kv, p_cm, p_ci, p_t0);
    add_ln_k<<<MROWS, 256>>>(p_t0, x, a1_g, a1_b, p_x1);

    // ---- MHA layer 2 ----
    gemm_bias_k<false><<<gProj, 256>>>(p_x1, DDIM, a2_Wq, DDIM, a2_bq, p_q,  DDIM, DDIM);
    gemm_bias_k<false><<<gProj, 256>>>(p_x1, DDIM, a2_Wv, DDIM, a2_bv, p_kv, DDIM, DDIM);
    attn_scores_k<<<gScore, 256>>>(p_q, p_kv, amask, p_w);
    col_softmax_k<<<gSoft, 256>>>(p_w, p_cm, p_ci);
    attn_out_k<<<gAO, 256>>>(p_w, p_kv, p_cm, p_ci, p_t0);
    add_ln_k<<<MROWS, 256>>>(p_t0, p_x1, a2_g, a2_b, p_x2);

    // ---- FFN ----
    gemm_bias_k<true ><<<gF1,   256>>>(p_x2, DDIM, f_W1, FFD,  f_b1, p_h,  FFD,  DDIM);
    gemm_bias_k<false><<<gProj, 256>>>(p_h,  FFD,  f_W2, DDIM, f_b2, p_t0, DDIM, FFD);
    add_ln_k<<<MROWS, 256>>>(p_t0, p_x2, f_g, f_b, out);
}

// round 9
// speedup vs baseline: 1.9668x; 1.9668x over previous
#include <cuda_runtime.h>
#include <cuda_bf16.h>
#include <cstdint>
#include <stdint.h>
#include <math.h>

#define BB   8
#define SS   1024
#define DDIM 768
#define HH   8
#define DKK  96
#define FFD  1024
#define BHN  (BB*HH)    // 64
#define MROWS (BB*SS)   // 8192

// ---------------- scratch (device globals: allocation-free rule) ------------
__device__ float g_q [MROWS*DDIM];
__device__ float g_kv[MROWS*DDIM];
__device__ float g_w [BHN*SS*SS];      // 256 MB score tensor
__device__ float g_cm[BHN*SS];         // per-column max
__device__ float g_ci[BHN*SS];         // per-column 1/sum
__device__ float g_t0[MROWS*DDIM];     // pre-LN buffer
__device__ float g_x1[MROWS*DDIM];     // layer1 out
__device__ float g_x2[MROWS*DDIM];     // layer2 out
__device__ float g_h [MROWS*FFD];      // FFN hidden
__device__ int   g_mask_u8;            // 1 if attention_mask is byte-packed

// ---------------- mask dtype probe -----------------------------------------
__global__ void probe_mask_k(const unsigned char* __restrict__ p) {
    __shared__ int any;
    if (threadIdx.x == 0) any = 0;
    __syncthreads();
    int local = 0;
    for (int i = threadIdx.x; i < BB*SS; i += 256)
        if ((i & 3) && p[i]) local = 1;
    if (local) atomicOr(&any, 1);
    __syncthreads();
    if (threadIdx.x == 0) g_mask_u8 = any;
}

// ---------------- bf16x3 helpers --------------------------------------------
// pack two consecutive-k elements into one b32 (low 16 bits = even-k element)
__device__ __forceinline__ void split2(float x, float y, uint32_t& h, uint32_t& l) {
    __nv_bfloat16 xh = __float2bfloat16(x);
    __nv_bfloat16 yh = __float2bfloat16(y);
    __nv_bfloat16 xl = __float2bfloat16(x - __bfloat162float(xh));
    __nv_bfloat16 yl = __float2bfloat16(y - __bfloat162float(yh));
    h = ((uint32_t)__bfloat16_as_ushort(yh) << 16) | (uint32_t)__bfloat16_as_ushort(xh);
    l = ((uint32_t)__bfloat16_as_ushort(yl) << 16) | (uint32_t)__bfloat16_as_ushort(xl);
}

__device__ __forceinline__ void mma16816(float* c, const uint32_t* a, const uint32_t* b) {
    asm volatile(
        "mma.sync.aligned.m16n8k16.row.col.f32.bf16.bf16.f32 "
        "{%0,%1,%2,%3}, {%4,%5,%6,%7}, {%8,%9}, {%0,%1,%2,%3};\n"
        : "+f"(c[0]), "+f"(c[1]), "+f"(c[2]), "+f"(c[3])
        : "r"(a[0]), "r"(a[1]), "r"(a[2]), "r"(a[3]), "r"(b[0]), "r"(b[1]));
}

// smem row stride (in b32 words): 136 ≡ 8 (mod 32) -> conflict-free frags
#define APAD 136
#define BPAD 136
#define BPAD96 104

// ============================================================================
// Generic GEMM: C[M,N] = A[M,K] @ B[K,N] + bias, optional ReLU.
// Block 128x128, 8 warps (2m x 4n), warp tile 64x32, BK=16, bf16x3.
// ============================================================================
template<bool RELU>
__global__ __launch_bounds__(256)
void gemm_tc(const float* __restrict__ A, int lda,
             const float* __restrict__ B, int ldb,
             const float* __restrict__ bias,
             float* __restrict__ C, int ldc, int K)
{
    __shared__ uint32_t sAh[8][APAD], sAl[8][APAD];
    __shared__ uint32_t sBh[8][BPAD], sBl[8][BPAD];

    const int tid = threadIdx.x;
    const int m0 = blockIdx.y * 128, n0 = blockIdx.x * 128;
    const int lane = tid & 31, warp = tid >> 5;
    const int wm = warp >> 2, wn = warp & 3;
    const int r = lane >> 2, kp = lane & 3;

    float2 aP[4]; float bPa[4], bPb[4];
    #pragma unroll
    for (int i = 0; i < 4; i++) {
        int p = tid + i * 256;
        int m = p >> 3, kq = p & 7;
        aP[i] = *(const float2*)&A[(size_t)(m0 + m) * lda + 2 * kq];
        int kb = p >> 7, n = p & 127;
        bPa[i] = B[(size_t)(2 * kb) * ldb + n0 + n];
        bPb[i] = B[(size_t)(2 * kb + 1) * ldb + n0 + n];
    }

    float c[4][4][4];
    #pragma unroll
    for (int i = 0; i < 4; i++)
        #pragma unroll
        for (int j = 0; j < 4; j++)
            #pragma unroll
            for (int e = 0; e < 4; e++) c[i][j][e] = 0.0f;

    const int KT = K >> 4;
    for (int kt = 0; kt < KT; kt++) {
        #pragma unroll
        for (int i = 0; i < 4; i++) {
            int p = tid + i * 256;
            int m = p >> 3, kq = p & 7;
            split2(aP[i].x, aP[i].y, sAh[kq][m], sAl[kq][m]);
            int kb = p >> 7, n = p & 127;
            split2(bPa[i], bPb[i], sBh[kb][n], sBl[kb][n]);
        }
        __syncthreads();
        if (kt + 1 < KT) {
            int k0 = (kt + 1) << 4;
            #pragma unroll
            for (int i = 0; i < 4; i++) {
                int p = tid + i * 256;
                int m = p >> 3, kq = p & 7;
                aP[i] = *(const float2*)&A[(size_t)(m0 + m) * lda + k0 + 2 * kq];
                int kb = p >> 7, n = p & 127;
                bPa[i] = B[(size_t)(k0 + 2 * kb) * ldb + n0 + n];
                bPb[i] = B[(size_t)(k0 + 2 * kb + 1) * ldb + n0 + n];
            }
        }
        uint32_t ah[4][4], al[4][4], bh[4][2], bl[4][2];
        #pragma unroll
        for (int ti = 0; ti < 4; ti++) {
            int row = wm * 64 + ti * 16 + r;
            ah[ti][0] = sAh[kp][row];     ah[ti][1] = sAh[kp][row + 8];
            ah[ti][2] = sAh[kp + 4][row]; ah[ti][3] = sAh[kp + 4][row + 8];
            al[ti][0] = sAl[kp][row];     al[ti][1] = sAl[kp][row + 8];
            al[ti][2] = sAl[kp + 4][row]; al[ti][3] = sAl[kp + 4][row + 8];
        }
        #pragma unroll
        for (int tj = 0; tj < 4; tj++) {
            int col = wn * 32 + tj * 8 + r;
            bh[tj][0] = sBh[kp][col]; bh[tj][1] = sBh[kp + 4][col];
            bl[tj][0] = sBl[kp][col]; bl[tj][1] = sBl[kp + 4][col];
        }
        #pragma unroll
        for (int ti = 0; ti < 4; ti++)
            #pragma unroll
            for (int tj = 0; tj < 4; tj++) {
                mma16816(c[ti][tj], ah[ti], bh[tj]);
                mma16816(c[ti][tj], ah[ti], bl[tj]);
                mma16816(c[ti][tj], al[ti], bh[tj]);
            }
        __syncthreads();
    }

    #pragma unroll
    for (int ti = 0; ti < 4; ti++) {
        int row = m0 + wm * 64 + ti * 16 + r;
        #pragma unroll
        for (int tj = 0; tj < 4; tj++) {
            int gc = n0 + wn * 32 + tj * 8 + 2 * kp;
            float b0 = bias[gc], b1 = bias[gc + 1];
            float v00 = c[ti][tj][0] + b0, v01 = c[ti][tj][1] + b1;
            float v10 = c[ti][tj][2] + b0, v11 = c[ti][tj][3] + b1;
            if (RELU) {
                v00 = fmaxf(v00, 0.f); v01 = fmaxf(v01, 0.f);
                v10 = fmaxf(v10, 0.f); v11 = fmaxf(v11, 0.f);
            }
            *(float2*)&C[(size_t)row * ldc + gc]       = make_float2(v00, v01);
            *(float2*)&C[(size_t)(row + 8) * ldc + gc] = make_float2(v10, v11);
        }
    }
}

// ============================================================================
// Attention scores: w[bh,q,k] = <q_row, k_row>/sqrt(DK), masked.
// Block 128x128 over (q,k); K=96. Causal block-skip writes -1e9 directly.
// ============================================================================
__global__ __launch_bounds__(256)
void attn_scores_tc(const float* __restrict__ q, const float* __restrict__ kv,
                    const void* __restrict__ pmask, float* __restrict__ w)
{
    const int bh = blockIdx.z, b = bh >> 3, h = bh & 7;
    const int m0 = blockIdx.y * 128;   // q tile
    const int n0 = blockIdx.x * 128;   // key tile
    const int tid = threadIdx.x;
    float* wo = w + (size_t)bh * SS * SS;

    if (n0 >= m0 + 128) {              // fully above diagonal: all masked
        const float4 f = make_float4(-1e9f, -1e9f, -1e9f, -1e9f);
        #pragma unroll
        for (int i = 0; i < 16; i++) {
            int p = tid + i * 256;
            int row = p >> 5, c4 = p & 31;
            *(float4*)&wo[(size_t)(m0 + row) * SS + n0 + c4 * 4] = f;
        }
        return;
    }

    __shared__ uint32_t sAh[8][APAD], sAl[8][APAD];
    __shared__ uint32_t sBh[8][APAD], sBl[8][APAD];

    const float* Ap = q  + (size_t)b * SS * DDIM + h * DKK;
    const float* Bp = kv + (size_t)b * SS * DDIM + h * DKK;
    const int lane = tid & 31, warp = tid >> 5;
    const int wm = warp >> 2, wn = warp & 3;
    const int r = lane >> 2, kp = lane & 3;

    float2 aP[4], bP[4];
    #pragma unroll
    for (int i = 0; i < 4; i++) {
        int p = tid + i * 256;
        int m = p >> 3, kq = p & 7;
        aP[i] = *(const float2*)&Ap[(size_t)(m0 + m) * DDIM + 2 * kq];
        bP[i] = *(const float2*)&Bp[(size_t)(n0 + m) * DDIM + 2 * kq];
    }

    float c[4][4][4];
    #pragma unroll
    for (int i = 0; i < 4; i++)
        #pragma unroll
        for (int j = 0; j < 4; j++)
            #pragma unroll
            for (int e = 0; e < 4; e++) c[i][j][e] = 0.0f;

    const int KT = DKK >> 4;   // 6
    for (int kt = 0; kt < KT; kt++) {
        #pragma unroll
        for (int i = 0; i < 4; i++) {
            int p = tid + i * 256;
            int m = p >> 3, kq = p & 7;
            split2(aP[i].x, aP[i].y, sAh[kq][m], sAl[kq][m]);
            split2(bP[i].x, bP[i].y, sBh[kq][m], sBl[kq][m]);
        }
        __syncthreads();
        if (kt + 1 < KT) {
            int k0 = (kt + 1) << 4;
            #pragma unroll
            for (int i = 0; i < 4; i++) {
                int p = tid + i * 256;
                int m = p >> 3, kq = p & 7;
                aP[i] = *(const float2*)&Ap[(size_t)(m0 + m) * DDIM + k0 + 2 * kq];
                bP[i] = *(const float2*)&Bp[(size_t)(n0 + m) * DDIM + k0 + 2 * kq];
            }
        }
        uint32_t ah[4][4], al[4][4], bh[4][2], bl[4][2];
        #pragma unroll
        for (int ti = 0; ti < 4; ti++) {
            int row = wm * 64 + ti * 16 + r;
            ah[ti][0] = sAh[kp][row];     ah[ti][1] = sAh[kp][row + 8];
            ah[ti][2] = sAh[kp + 4][row]; ah[ti][3] = sAh[kp + 4][row + 8];
            al[ti][0] = sAl[kp][row];     al[ti][1] = sAl[kp][row + 8];
            al[ti][2] = sAl[kp + 4][row]; al[ti][3] = sAl[kp + 4][row + 8];
        }
        #pragma unroll
        for (int tj = 0; tj < 4; tj++) {
            int col = wn * 32 + tj * 8 + r;
            bh[tj][0] = sBh[kp][col]; bh[tj][1] = sBh[kp + 4][col];
            bl[tj][0] = sBl[kp][col]; bl[tj][1] = sBl[kp + 4][col];
        }
        #pragma unroll
        for (int ti = 0; ti < 4; ti++)
            #pragma unroll
            for (int tj = 0; tj < 4; tj++) {
                mma16816(c[ti][tj], ah[ti], bh[tj]);
                mma16816(c[ti][tj], ah[ti], bl[tj]);
                mma16816(c[ti][tj], al[ti], bh[tj]);
            }
        __syncthreads();
    }

    const float scale = 0.10206207261596575f;   // 1/sqrt(96)
    const unsigned char* m8  = (const unsigned char*)pmask;
    const int*           m32 = (const int*)pmask;
    const int u8 = g_mask_u8;
    #pragma unroll
    for (int ti = 0; ti < 4; ti++) {
        int qrA = m0 + wm * 64 + ti * 16 + r;
        int qrB = qrA + 8;
        int padA = u8 ? (int)m8[b * SS + qrA] : m32[b * SS + qrA];
        int padB = u8 ? (int)m8[b * SS + qrB] : m32[b * SS + qrB];
        #pragma unroll
        for (int tj = 0; tj < 4; tj++) {
            int gc = n0 + wn * 32 + tj * 8 + 2 * kp;
            float v00 = ((gc     > qrA) || padA) ? -1e9f : c[ti][tj][0] * scale;
            float v01 = ((gc + 1 > qrA) || padA) ? -1e9f : c[ti][tj][1] * scale;
            float v10 = ((gc     > qrB) || padB) ? -1e9f : c[ti][tj][2] * scale;
            float v11 = ((gc + 1 > qrB) || padB) ? -1e9f : c[ti][tj][3] * scale;
            *(float2*)&wo[(size_t)qrA * SS + gc] = make_float2(v00, v01);
            *(float2*)&wo[(size_t)qrB * SS + gc] = make_float2(v10, v11);
        }
    }
}

// ---------------- online column softmax stats (softmax over q axis!) --------
__global__ void col_softmax_k(const float* __restrict__ w,
                              float* __restrict__ cm, float* __restrict__ ci)
{
    const int bh = blockIdx.y;
    const int k  = blockIdx.x * 256 + threadIdx.x;
    const float* wc = w + (size_t)bh * SS * SS + k;
    float m = -1e30f, s = 0.0f;
    for (int q = 0; q < SS; q++) {
        float v = wc[(size_t)q * SS];
        if (v > m) { s = s * expf(m - v) + 1.0f; m = v; }
        else       { s += expf(v - m); }
    }
    cm[bh * SS + k] = m;
    ci[bh * SS + k] = 1.0f / s;
}

// ============================================================================
// o = softmax(w) @ v. Block 128x96, 8 warps (2m x 4n), warp tile 64x24.
// exp(w - cm[k]) * ci[k] applied at the A-tile split (once per element).
// ============================================================================
__global__ __launch_bounds__(256)
void attn_out_tc(const float* __restrict__ w, const float* __restrict__ kv,
                 const float* __restrict__ cm, const float* __restrict__ ci,
                 float* __restrict__ o)
{
    __shared__ uint32_t sAh[8][APAD], sAl[8][APAD];
    __shared__ uint32_t sBh[8][BPAD96], sBl[8][BPAD96];

    const int bh = blockIdx.y, b = bh >> 3, h = bh & 7;
    const int m0 = blockIdx.x * 128;
    const float* Ap  = w  + (size_t)bh * SS * SS;
    const float* Bp  = kv + (size_t)b * SS * DDIM + h * DKK;
    const float* cmp = cm + bh * SS;
    const float* cip = ci + bh * SS;
    const int tid = threadIdx.x;
    const int lane = tid & 31, warp = tid >> 5;
    const int wm = warp >> 2, wn = warp & 3;
    const int r = lane >> 2, kp = lane & 3;

    float2 aP[4]; float bPa[3], bPb[3];
    #pragma unroll
    for (int i = 0; i < 4; i++) {
        int p = tid + i * 256;
        int m = p >> 3, kq = p & 7;
        aP[i] = *(const float2*)&Ap[(size_t)(m0 + m) * SS + 2 * kq];
    }
    #pragma unroll
    for (int i = 0; i < 3; i++) {
        int p = tid + i * 256;
        int kq = p / 96, n = p - kq * 96;
        const float* base = &Bp[(size_t)(2 * kq) * DDIM + n];
        bPa[i] = base[0]; bPb[i] = base[DDIM];
    }

    float c[4][3][4];
    #pragma unroll
    for (int i = 0; i < 4; i++)
        #pragma unroll
        for (int j = 0; j < 3; j++)
            #pragma unroll
            for (int e = 0; e < 4; e++) c[i][j][e] = 0.0f;

    const int KT = SS >> 4;   // 64
    for (int kt = 0; kt < KT; kt++) {
        const int kb0 = kt << 4;
        #pragma unroll
        for (int i = 0; i < 4; i++) {
            int p = tid + i * 256;
            int m = p >> 3, kq = p & 7;
            int kk = kb0 + 2 * kq;
            float px = expf(aP[i].x - cmp[kk])     * cip[kk];
            float py = expf(aP[i].y - cmp[kk + 1]) * cip[kk + 1];
            split2(px, py, sAh[kq][m], sAl[kq][m]);
        }
        #pragma unroll
        for (int i = 0; i < 3; i++) {
            int p = tid + i * 256;
            int kq = p / 96, n = p - kq * 96;
            split2(bPa[i], bPb[i], sBh[kq][n], sBl[kq][n]);
        }
        __syncthreads();
        if (kt + 1 < KT) {
            int k0 = (kt + 1) << 4;
            #pragma unroll
            for (int i = 0; i < 4; i++) {
                int p = tid + i * 256;
                int m = p >> 3, kq = p & 7;
                aP[i] = *(const float2*)&Ap[(size_t)(m0 + m) * SS + k0 + 2 * kq];
            }
            #pragma unroll
            for (int i = 0; i < 3; i++) {
                int p = tid + i * 256;
                int kq = p / 96, n = p - kq * 96;
                const float* base = &Bp[(size_t)(k0 + 2 * kq) * DDIM + n];
                bPa[i] = base[0]; bPb[i] = base[DDIM];
            }
        }
        uint32_t ah[4][4], al[4][4], bh[3][2], bl[3][2];
        #pragma unroll
        for (int ti = 0; ti < 4; ti++) {
            int row = wm * 64 + ti * 16 + r;
            ah[ti][0] = sAh[kp][row];     ah[ti][1] = sAh[kp][row + 8];
            ah[ti][2] = sAh[kp + 4][row]; ah[ti][3] = sAh[kp + 4][row + 8];
            al[ti][0] = sAl[kp][row];     al[ti][1] = sAl[kp][row + 8];
            al[ti][2] = sAl[kp + 4][row]; al[ti][3] = sAl[kp + 4][row + 8];
        }
        #pragma unroll
        for (int tj = 0; tj < 3; tj++) {
            int col = wn * 24 + tj * 8 + r;
            bh[tj][0] = sBh[kp][col]; bh[tj][1] = sBh[kp + 4][col];
            bl[tj][0] = sBl[kp][col]; bl[tj][1] = sBl[kp + 4][col];
        }
        #pragma unroll
        for (int ti = 0; ti < 4; ti++)
            #pragma unroll
            for (int tj = 0; tj < 3; tj++) {
                mma16816(c[ti][tj], ah[ti], bh[tj]);
                mma16816(c[ti][tj], ah[ti], bl[tj]);
                mma16816(c[ti][tj], al[ti], bh[tj]);
            }
        __syncthreads();
    }

    #pragma unroll
    for (int ti = 0; ti < 4; ti++) {
        int row = m0 + wm * 64 + ti * 16 + r;
        float* oA = o + (size_t)(b * SS + row) * DDIM + h * DKK;
        float* oB = o + (size_t)(b * SS + row + 8) * DDIM + h * DKK;
        #pragma unroll
        for (int tj = 0; tj < 3; tj++) {
            int gc = wn * 24 + tj * 8 + 2 * kp;
            *(float2*)&oA[gc] = make_float2(c[ti][tj][0], c[ti][tj][1]);
            *(float2*)&oB[gc] = make_float2(c[ti][tj][2], c[ti][tj][3]);
        }
    }
}

// ---------------- fused residual + LayerNorm --------------------------------
__global__ void add_ln_k(const float* __restrict__ o, const float* __restrict__ x,
                         const float* __restrict__ g, const float* __restrict__ bta,
                         float* __restrict__ out)
{
    __shared__ float red[256];
    const int row = blockIdx.x;
    const int tid = threadIdx.x;
    const float* op = o + (size_t)row * DDIM;
    const float* xp = x + (size_t)row * DDIM;
    float v[3];
    float lsum = 0.0f;
    #pragma unroll
    for (int i = 0; i < 3; i++) {
        int c = tid + i * 256;
        v[i] = op[c] + xp[c];
        lsum += v[i];
    }
    red[tid] = lsum; __syncthreads();
    for (int st = 128; st > 0; st >>= 1) {
        if (tid < st) red[tid] += red[tid + st];
        __syncthreads();
    }
    float mean = red[0] * (1.0f / 768.0f);
    __syncthreads();
    float lsq = 0.0f;
    #pragma unroll
    for (int i = 0; i < 3; i++) { float d = v[i] - mean; lsq += d * d; }
    red[tid] = lsq; __syncthreads();
    for (int st = 128; st > 0; st >>= 1) {
        if (tid < st) red[tid] += red[tid + st];
        __syncthreads();
    }
    float inv = rsqrtf(red[0] * (1.0f / 768.0f) + 1e-5f);
    #pragma unroll
    for (int i = 0; i < 3; i++) {
        int c = tid + i * 256;
        out[(size_t)row * DDIM + c] = (v[i] - mean) * inv * g[c] + bta[c];
    }
}

// ---------------- launch -----------------------------------------------------
extern "C" void kernel_launch(void* const* d_in, const int* in_sizes, int n_in,
                              void* d_out, int out_size)
{
    const float* x     = (const float*)d_in[0];
    const void*  amask = d_in[1];
    const float* a1_Wq = (const float*)d_in[2],  *a1_bq = (const float*)d_in[3];
    const float* a1_Wv = (const float*)d_in[4],  *a1_bv = (const float*)d_in[5];
    const float* a1_g  = (const float*)d_in[6],  *a1_b  = (const float*)d_in[7];
    const float* a2_Wq = (const float*)d_in[8],  *a2_bq = (const float*)d_in[9];
    const float* a2_Wv = (const float*)d_in[10], *a2_bv = (const float*)d_in[11];
    const float* a2_g  = (const float*)d_in[12], *a2_b  = (const float*)d_in[13];
    const float* f_W1  = (const float*)d_in[14], *f_b1  = (const float*)d_in[15];
    const float* f_W2  = (const float*)d_in[16], *f_b2  = (const float*)d_in[17];
    const float* f_g   = (const float*)d_in[18], *f_b   = (const float*)d_in[19];
    float* out = (float*)d_out;

    float *p_q, *p_kv, *p_w, *p_cm, *p_ci, *p_t0, *p_x1, *p_x2, *p_h;
    cudaGetSymbolAddress((void**)&p_q,  g_q);
    cudaGetSymbolAddress((void**)&p_kv, g_kv);
    cudaGetSymbolAddress((void**)&p_w,  g_w);
    cudaGetSymbolAddress((void**)&p_cm, g_cm);
    cudaGetSymbolAddress((void**)&p_ci, g_ci);
    cudaGetSymbolAddress((void**)&p_t0, g_t0);
    cudaGetSymbolAddress((void**)&p_x1, g_x1);
    cudaGetSymbolAddress((void**)&p_x2, g_x2);
    cudaGetSymbolAddress((void**)&p_h,  g_h);

    probe_mask_k<<<1, 256>>>((const unsigned char*)amask);

    const dim3 gProj(6, 64);             // N=768, M=8192, 128x128 tiles
    const dim3 gScore(8, 8, 64);         // key-tiles, q-tiles, bh
    const dim3 gSoft(4, 64);
    const dim3 gAO(8, 64);               // q-tiles, bh
    const dim3 gF1(8, 64);               // N=1024

    // ---- MHA layer 1 ----
    gemm_tc<false><<<gProj, 256>>>(x, DDIM, a1_Wq, DDIM, a1_bq, p_q,  DDIM, DDIM);
    gemm_tc<false><<<gProj, 256>>>(x, DDIM, a1_Wv, DDIM, a1_bv, p_kv, DDIM, DDIM);
    attn_scores_tc<<<gScore, 256>>>(p_q, p_kv, amask, p_w);
    col_softmax_k<<<gSoft, 256>>>(p_w, p_cm, p_ci);
    attn_out_tc<<<gAO, 256>>>(p_w, p_kv, p_cm, p_ci, p_t0);
    add_ln_k<<<MROWS, 256>>>(p_t0, x, a1_g, a1_b, p_x1);

    // ---- MHA layer 2 ----
    gemm_tc<false><<<gProj, 256>>>(p_x1, DDIM, a2_Wq, DDIM, a2_bq, p_q,  DDIM, DDIM);
    gemm_tc<false><<<gProj, 256>>>(p_x1, DDIM, a2_Wv, DDIM, a2_bv, p_kv, DDIM, DDIM);
    attn_scores_tc<<<gScore, 256>>>(p_q, p_kv, amask, p_w);
    col_softmax_k<<<gSoft, 256>>>(p_w, p_cm, p_ci);
    attn_out_tc<<<gAO, 256>>>(p_w, p_kv, p_cm, p_ci, p_t0);
    add_ln_k<<<MROWS, 256>>>(p_t0, p_x1, a2_g, a2_b, p_x2);

    // ---- FFN ----
    gemm_tc<true ><<<gF1,   256>>>(p_x2, DDIM, f_W1, FFD,  f_b1, p_h,  FFD,  DDIM);
    gemm_tc<false><<<gProj, 256>>>(p_h,  FFD,  f_W2, DDIM, f_b2, p_t0, DDIM, FFD);
    add_ln_k<<<MROWS, 256>>>(p_t0, p_x2, f_g, f_b, out);
}

// round 10
// speedup vs baseline: 2.0705x; 1.0527x over previous
#include <cuda_runtime.h>
#include <cuda_bf16.h>
#include <cstdint>
#include <stdint.h>
#include <math.h>

#define BB   8
#define SS   1024
#define DDIM 768
#define HH   8
#define DKK  96
#define FFD  1024
#define BHN  (BB*HH)    // 64
#define MROWS (BB*SS)   // 8192
#define DP   (DDIM/2)   // 384 pairs
#define FP   (FFD/2)    // 512 pairs

// ---------------- scratch (device globals: allocation-free rule) ------------
__device__ float g_w [BHN*SS*SS];      // 256 MB score tensor (lower-tri only valid)
__device__ float g_cm[BHN*SS];
__device__ float g_ci[BHN*SS];
__device__ float g_kv[MROWS*DDIM];     // f32 kv (attn_out B operand)
__device__ float g_t0[MROWS*DDIM];
__device__ float g_x1[MROWS*DDIM];
__device__ float g_x2[MROWS*DDIM];
__device__ int   g_mask_u8;

// packed bf16 hi/lo buffers (u32 = 2 consecutive-k elements)
__device__ uint32_t g_xh [MROWS*DP],  g_xl [MROWS*DP];
__device__ uint32_t g_qh [MROWS*DP],  g_ql [MROWS*DP];
__device__ uint32_t g_kvh[MROWS*DP],  g_kvl[MROWS*DP];
__device__ uint32_t g_x1h[MROWS*DP],  g_x1l[MROWS*DP];
__device__ uint32_t g_x2h[MROWS*DP],  g_x2l[MROWS*DP];
__device__ uint32_t g_hh [MROWS*FP],  g_hl [MROWS*FP];
__device__ uint32_t g_w1qh[DP*DDIM], g_w1ql[DP*DDIM];
__device__ uint32_t g_w1vh[DP*DDIM], g_w1vl[DP*DDIM];
__device__ uint32_t g_w2qh[DP*DDIM], g_w2ql[DP*DDIM];
__device__ uint32_t g_w2vh[DP*DDIM], g_w2vl[DP*DDIM];
__device__ uint32_t g_wf1h[DP*FFD],  g_wf1l[DP*FFD];
__device__ uint32_t g_wf2h[FP*DDIM], g_wf2l[FP*DDIM];

// ---------------- mask dtype probe -----------------------------------------
__global__ void probe_mask_k(const unsigned char* __restrict__ p) {
    __shared__ int any;
    if (threadIdx.x == 0) any = 0;
    __syncthreads();
    int local = 0;
    for (int i = threadIdx.x; i < BB*SS; i += 256)
        if ((i & 3) && p[i]) local = 1;
    if (local) atomicOr(&any, 1);
    __syncthreads();
    if (threadIdx.x == 0) g_mask_u8 = any;
}

// ---------------- bf16x3 helpers --------------------------------------------
__device__ __forceinline__ void split2(float x, float y, uint32_t& h, uint32_t& l) {
    __nv_bfloat16 xh = __float2bfloat16(x);
    __nv_bfloat16 yh = __float2bfloat16(y);
    __nv_bfloat16 xl = __float2bfloat16(x - __bfloat162float(xh));
    __nv_bfloat16 yl = __float2bfloat16(y - __bfloat162float(yh));
    h = ((uint32_t)__bfloat16_as_ushort(yh) << 16) | (uint32_t)__bfloat16_as_ushort(xh);
    l = ((uint32_t)__bfloat16_as_ushort(yl) << 16) | (uint32_t)__bfloat16_as_ushort(xl);
}

__device__ __forceinline__ void mma16816(float* c, const uint32_t* a, const uint32_t* b) {
    asm volatile(
        "mma.sync.aligned.m16n8k16.row.col.f32.bf16.bf16.f32 "
        "{%0,%1,%2,%3}, {%4,%5,%6,%7}, {%8,%9}, {%0,%1,%2,%3};\n"
        : "+f"(c[0]), "+f"(c[1]), "+f"(c[2]), "+f"(c[3])
        : "r"(a[0]), "r"(a[1]), "r"(a[2]), "r"(a[3]), "r"(b[0]), "r"(b[1]));
}

#define APAD 136
#define BPAD 136
#define BPAD96 104

// ---------------- one-time split kernels -------------------------------------
// row-pack: source row-major [M,K], pairs contiguous over k
__global__ void split_rows_k(const float* __restrict__ s, uint32_t* __restrict__ dh,
                             uint32_t* __restrict__ dl, int npairs) {
    int p = blockIdx.x * 256 + threadIdx.x;
    if (p >= npairs) return;
    float2 v = *(const float2*)&s[(size_t)2 * p];
    split2(v.x, v.y, dh[p], dl[p]);
}
// col-pack: source [K,N] row-major; pair elements stride N apart (for B operands)
__global__ void split_cols_k(const float* __restrict__ s, uint32_t* __restrict__ dh,
                             uint32_t* __restrict__ dl, int N, int npairs) {
    int p = blockIdx.x * 256 + threadIdx.x;
    if (p >= npairs) return;
    int kq = p / N, n = p - kq * N;
    split2(s[(size_t)(2 * kq) * N + n], s[(size_t)(2 * kq + 1) * N + n], dh[p], dl[p]);
}

// ============================================================================
// Generic GEMM (packed operands): C = A@B + bias, optional ReLU.
// A packed [M][K/2] u32, B packed [K/2][N] u32. Outputs: f32 and/or packed.
// Block 128x128, 8 warps, warp tile 64x32, BK=16 (8 pairs), bf16x3.
// ============================================================================
template<bool RELU, bool WF32, bool WPACK>
__global__ __launch_bounds__(256)
void gemm_tc(const uint32_t* __restrict__ Ah, const uint32_t* __restrict__ Al, int ldap,
             const uint32_t* __restrict__ Bh, const uint32_t* __restrict__ Bl, int ldb,
             const float* __restrict__ bias,
             float* __restrict__ C, uint32_t* __restrict__ Ch, uint32_t* __restrict__ Cl,
             int ldc, int K)
{
    __shared__ uint32_t sAh[8][APAD], sAl[8][APAD];
    __shared__ uint32_t sBh[8][BPAD], sBl[8][BPAD];

    const int tid = threadIdx.x;
    const int m0 = blockIdx.y * 128, n0 = blockIdx.x * 128;
    const int lane = tid & 31, warp = tid >> 5;
    const int wm = warp >> 2, wn = warp & 3;
    const int r = lane >> 2, kp = lane & 3;

    uint32_t aH[4], aL[4], bH[4], bL[4];
    #pragma unroll
    for (int i = 0; i < 4; i++) {
        int p = tid + i * 256;
        int m = p >> 3, kq = p & 7;
        aH[i] = Ah[(size_t)(m0 + m) * ldap + kq];
        aL[i] = Al[(size_t)(m0 + m) * ldap + kq];
        int kb = p >> 7, n = p & 127;
        bH[i] = Bh[(size_t)kb * ldb + n0 + n];
        bL[i] = Bl[(size_t)kb * ldb + n0 + n];
    }

    float c[4][4][4];
    #pragma unroll
    for (int i = 0; i < 4; i++)
        #pragma unroll
        for (int j = 0; j < 4; j++)
            #pragma unroll
            for (int e = 0; e < 4; e++) c[i][j][e] = 0.0f;

    const int KT = K >> 4;
    for (int kt = 0; kt < KT; kt++) {
        #pragma unroll
        for (int i = 0; i < 4; i++) {
            int p = tid + i * 256;
            int m = p >> 3, kq = p & 7;
            sAh[kq][m] = aH[i]; sAl[kq][m] = aL[i];
            int kb = p >> 7, n = p & 127;
            sBh[kb][n] = bH[i]; sBl[kb][n] = bL[i];
        }
        __syncthreads();
        if (kt + 1 < KT) {
            int kq0 = (kt + 1) * 8;
            #pragma unroll
            for (int i = 0; i < 4; i++) {
                int p = tid + i * 256;
                int m = p >> 3, kq = p & 7;
                aH[i] = Ah[(size_t)(m0 + m) * ldap + kq0 + kq];
                aL[i] = Al[(size_t)(m0 + m) * ldap + kq0 + kq];
                int kb = p >> 7, n = p & 127;
                bH[i] = Bh[(size_t)(kq0 + kb) * ldb + n0 + n];
                bL[i] = Bl[(size_t)(kq0 + kb) * ldb + n0 + n];
            }
        }
        uint32_t ah[4][4], al[4][4], bh[4][2], bl[4][2];
        #pragma unroll
        for (int ti = 0; ti < 4; ti++) {
            int row = wm * 64 + ti * 16 + r;
            ah[ti][0] = sAh[kp][row];     ah[ti][1] = sAh[kp][row + 8];
            ah[ti][2] = sAh[kp + 4][row]; ah[ti][3] = sAh[kp + 4][row + 8];
            al[ti][0] = sAl[kp][row];     al[ti][1] = sAl[kp][row + 8];
            al[ti][2] = sAl[kp + 4][row]; al[ti][3] = sAl[kp + 4][row + 8];
        }
        #pragma unroll
        for (int tj = 0; tj < 4; tj++) {
            int col = wn * 32 + tj * 8 + r;
            bh[tj][0] = sBh[kp][col]; bh[tj][1] = sBh[kp + 4][col];
            bl[tj][0] = sBl[kp][col]; bl[tj][1] = sBl[kp + 4][col];
        }
        #pragma unroll
        for (int ti = 0; ti < 4; ti++)
            #pragma unroll
            for (int tj = 0; tj < 4; tj++) {
                mma16816(c[ti][tj], ah[ti], bh[tj]);
                mma16816(c[ti][tj], ah[ti], bl[tj]);
                mma16816(c[ti][tj], al[ti], bh[tj]);
            }
        __syncthreads();
    }

    #pragma unroll
    for (int ti = 0; ti < 4; ti++) {
        int row = m0 + wm * 64 + ti * 16 + r;
        #pragma unroll
        for (int tj = 0; tj < 4; tj++) {
            int gc = n0 + wn * 32 + tj * 8 + 2 * kp;
            float b0 = bias[gc], b1 = bias[gc + 1];
            float v00 = c[ti][tj][0] + b0, v01 = c[ti][tj][1] + b1;
            float v10 = c[ti][tj][2] + b0, v11 = c[ti][tj][3] + b1;
            if (RELU) {
                v00 = fmaxf(v00, 0.f); v01 = fmaxf(v01, 0.f);
                v10 = fmaxf(v10, 0.f); v11 = fmaxf(v11, 0.f);
            }
            if (WF32) {
                *(float2*)&C[(size_t)row * ldc + gc]       = make_float2(v00, v01);
                *(float2*)&C[(size_t)(row + 8) * ldc + gc] = make_float2(v10, v11);
            }
            if (WPACK) {
                int ldcp = ldc >> 1, gp = gc >> 1;
                uint32_t ph, pl;
                split2(v00, v01, ph, pl);
                Ch[(size_t)row * ldcp + gp] = ph; Cl[(size_t)row * ldcp + gp] = pl;
                split2(v10, v11, ph, pl);
                Ch[(size_t)(row + 8) * ldcp + gp] = ph; Cl[(size_t)(row + 8) * ldcp + gp] = pl;
            }
        }
    }
}

// ============================================================================
// Attention scores (packed q/kv): w = q·k^T/sqrt(DK), masked; above-diagonal
// tiles are NEVER written (consumers never read them).
// ============================================================================
__global__ __launch_bounds__(256)
void attn_scores_tc(const uint32_t* __restrict__ qh, const uint32_t* __restrict__ ql,
                    const uint32_t* __restrict__ kvh, const uint32_t* __restrict__ kvl,
                    const void* __restrict__ pmask, float* __restrict__ w)
{
    const int bh = blockIdx.z, b = bh >> 3, h = bh & 7;
    const int m0 = blockIdx.y * 128;   // q tile
    const int n0 = blockIdx.x * 128;   // key tile
    if (n0 >= m0 + 128) return;        // fully-masked tile: not stored at all

    __shared__ uint32_t sAh[8][APAD], sAl[8][APAD];
    __shared__ uint32_t sBh[8][APAD], sBl[8][APAD];

    const uint32_t* Aph = qh  + (size_t)b * SS * DP + h * (DKK / 2);
    const uint32_t* Apl = ql  + (size_t)b * SS * DP + h * (DKK / 2);
    const uint32_t* Bph = kvh + (size_t)b * SS * DP + h * (DKK / 2);
    const uint32_t* Bpl = kvl + (size_t)b * SS * DP + h * (DKK / 2);

    const int tid = threadIdx.x;
    const int lane = tid & 31, warp = tid >> 5;
    const int wm = warp >> 2, wn = warp & 3;
    const int r = lane >> 2, kp = lane & 3;

    uint32_t aH[4], aL[4], bH[4], bL[4];
    #pragma unroll
    for (int i = 0; i < 4; i++) {
        int p = tid + i * 256;
        int m = p >> 3, kq = p & 7;
        aH[i] = Aph[(size_t)(m0 + m) * DP + kq];
        aL[i] = Apl[(size_t)(m0 + m) * DP + kq];
        bH[i] = Bph[(size_t)(n0 + m) * DP + kq];
        bL[i] = Bpl[(size_t)(n0 + m) * DP + kq];
    }

    float c[4][4][4];
    #pragma unroll
    for (int i = 0; i < 4; i++)
        #pragma unroll
        for (int j = 0; j < 4; j++)
            #pragma unroll
            for (int e = 0; e < 4; e++) c[i][j][e] = 0.0f;

    const int KT = DKK >> 4;   // 6
    for (int kt = 0; kt < KT; kt++) {
        #pragma unroll
        for (int i = 0; i < 4; i++) {
            int p = tid + i * 256;
            int m = p >> 3, kq = p & 7;
            sAh[kq][m] = aH[i]; sAl[kq][m] = aL[i];
            sBh[kq][m] = bH[i]; sBl[kq][m] = bL[i];
        }
        __syncthreads();
        if (kt + 1 < KT) {
            int kq0 = (kt + 1) * 8;
            #pragma unroll
            for (int i = 0; i < 4; i++) {
                int p = tid + i * 256;
                int m = p >> 3, kq = p & 7;
                aH[i] = Aph[(size_t)(m0 + m) * DP + kq0 + kq];
                aL[i] = Apl[(size_t)(m0 + m) * DP + kq0 + kq];
                bH[i] = Bph[(size_t)(n0 + m) * DP + kq0 + kq];
                bL[i] = Bpl[(size_t)(n0 + m) * DP + kq0 + kq];
            }
        }
        uint32_t ah[4][4], al[4][4], bh[4][2], bl[4][2];
        #pragma unroll
        for (int ti = 0; ti < 4; ti++) {
            int row = wm * 64 + ti * 16 + r;
            ah[ti][0] = sAh[kp][row];     ah[ti][1] = sAh[kp][row + 8];
            ah[ti][2] = sAh[kp + 4][row]; ah[ti][3] = sAh[kp + 4][row + 8];
            al[ti][0] = sAl[kp][row];     al[ti][1] = sAl[kp][row + 8];
            al[ti][2] = sAl[kp + 4][row]; al[ti][3] = sAl[kp + 4][row + 8];
        }
        #pragma unroll
        for (int tj = 0; tj < 4; tj++) {
            int col = wn * 32 + tj * 8 + r;
            bh[tj][0] = sBh[kp][col]; bh[tj][1] = sBh[kp + 4][col];
            bl[tj][0] = sBl[kp][col]; bl[tj][1] = sBl[kp + 4][col];
        }
        #pragma unroll
        for (int ti = 0; ti < 4; ti++)
            #pragma unroll
            for (int tj = 0; tj < 4; tj++) {
                mma16816(c[ti][tj], ah[ti], bh[tj]);
                mma16816(c[ti][tj], ah[ti], bl[tj]);
                mma16816(c[ti][tj], al[ti], bh[tj]);
            }
        __syncthreads();
    }

    const float scale = 0.10206207261596575f;   // 1/sqrt(96)
    const unsigned char* m8  = (const unsigned char*)pmask;
    const int*           m32 = (const int*)pmask;
    const int u8 = g_mask_u8;
    float* wo = w + (size_t)bh * SS * SS;
    #pragma unroll
    for (int ti = 0; ti < 4; ti++) {
        int qrA = m0 + wm * 64 + ti * 16 + r;
        int qrB = qrA + 8;
        int padA = u8 ? (int)m8[b * SS + qrA] : m32[b * SS + qrA];
        int padB = u8 ? (int)m8[b * SS + qrB] : m32[b * SS + qrB];
        #pragma unroll
        for (int tj = 0; tj < 4; tj++) {
            int gc = n0 + wn * 32 + tj * 8 + 2 * kp;
            float v00 = ((gc     > qrA) || padA) ? -1e9f : c[ti][tj][0] * scale;
            float v01 = ((gc + 1 > qrA) || padA) ? -1e9f : c[ti][tj][1] * scale;
            float v10 = ((gc     > qrB) || padB) ? -1e9f : c[ti][tj][2] * scale;
            float v11 = ((gc + 1 > qrB) || padB) ? -1e9f : c[ti][tj][3] * scale;
            *(float2*)&wo[(size_t)qrA * SS + gc] = make_float2(v00, v01);
            *(float2*)&wo[(size_t)qrB * SS + gc] = make_float2(v10, v11);
        }
    }
}

// ---------------- online column softmax (over q axis) with causal skip ------
// Rows q < (k & ~127) are analytically -1e9 (never stored): scan starts at the
// column's 128-tile and the skipped mass is added in closed form.
__global__ void col_softmax_k(const float* __restrict__ w,
                              float* __restrict__ cm, float* __restrict__ ci)
{
    const int bh = blockIdx.y;
    const int k  = blockIdx.x * 256 + threadIdx.x;
    const int qs = k & ~127;             // warp-uniform (32 consecutive k share tile)
    const float* wc = w + (size_t)bh * SS * SS + k;
    float m = -1e30f, s = 0.0f;
    for (int q = qs; q < SS; q++) {
        float v = wc[(size_t)q * SS];
        if (v > m) { s = s * expf(m - v) + 1.0f; m = v; }
        else       { s += expf(v - m); }
    }
    s += (float)qs * expf(-1e9f - m);    // skipped rows: all exactly -1e9
    cm[bh * SS + k] = m;
    ci[bh * SS + k] = 1.0f / s;
}

// ============================================================================
// o = softmax(w) @ v. Block 128x96. For k-tiles fully above the diagonal the
// w value is the constant -1e9 (not stored) — no gmem read.
// ============================================================================
__global__ __launch_bounds__(256)
void attn_out_tc(const float* __restrict__ w, const float* __restrict__ kv,
                 const float* __restrict__ cm, const float* __restrict__ ci,
                 float* __restrict__ o)
{
    __shared__ uint32_t sAh[8][APAD], sAl[8][APAD];
    __shared__ uint32_t sBh[8][BPAD96], sBl[8][BPAD96];

    const int bh = blockIdx.y, b = bh >> 3, h = bh & 7;
    const int m0 = blockIdx.x * 128;
    const float* Ap  = w  + (size_t)bh * SS * SS;
    const float* Bp  = kv + (size_t)b * SS * DDIM + h * DKK;
    const float* cmp = cm + bh * SS;
    const float* cip = ci + bh * SS;
    const int tid = threadIdx.x;
    const int lane = tid & 31, warp = tid >> 5;
    const int wm = warp >> 2, wn = warp & 3;
    const int r = lane >> 2, kp = lane & 3;

    float2 aP[4]; float bPa[3], bPb[3];
    #pragma unroll
    for (int i = 0; i < 4; i++) {
        int p = tid + i * 256;
        int m = p >> 3, kq = p & 7;
        aP[i] = *(const float2*)&Ap[(size_t)(m0 + m) * SS + 2 * kq];
    }
    #pragma unroll
    for (int i = 0; i < 3; i++) {
        int p = tid + i * 256;
        int kq = p / 96, n = p - kq * 96;
        const float* base = &Bp[(size_t)(2 * kq) * DDIM + n];
        bPa[i] = base[0]; bPb[i] = base[DDIM];
    }

    float c[4][3][4];
    #pragma unroll
    for (int i = 0; i < 4; i++)
        #pragma unroll
        for (int j = 0; j < 3; j++)
            #pragma unroll
            for (int e = 0; e < 4; e++) c[i][j][e] = 0.0f;

    const int KT = SS >> 4;   // 64
    for (int kt = 0; kt < KT; kt++) {
        const int kb0 = kt << 4;
        const bool above = kb0 >= m0 + 128;    // whole tile above diagonal
        #pragma unroll
        for (int i = 0; i < 4; i++) {
            int p = tid + i * 256;
            int m = p >> 3, kq = p & 7;
            int kk = kb0 + 2 * kq;
            float rawx = above ? -1e9f : aP[i].x;
            float rawy = above ? -1e9f : aP[i].y;
            float px = expf(rawx - cmp[kk])     * cip[kk];
            float py = expf(rawy - cmp[kk + 1]) * cip[kk + 1];
            split2(px, py, sAh[kq][m], sAl[kq][m]);
        }
        #pragma unroll
        for (int i = 0; i < 3; i++) {
            int p = tid + i * 256;
            int kq = p / 96, n = p - kq * 96;
            split2(bPa[i], bPb[i], sBh[kq][n], sBl[kq][n]);
        }
        __syncthreads();
        if (kt + 1 < KT) {
            int k0 = (kt + 1) << 4;
            if (k0 < m0 + 128) {               // next tile reads stored w
                #pragma unroll
                for (int i = 0; i < 4; i++) {
                    int p = tid + i * 256;
                    int m = p >> 3, kq = p & 7;
                    aP[i] = *(const float2*)&Ap[(size_t)(m0 + m) * SS + k0 + 2 * kq];
                }
            }
            #pragma unroll
            for (int i = 0; i < 3; i++) {
                int p = tid + i * 256;
                int kq = p / 96, n = p - kq * 96;
                const float* base = &Bp[(size_t)(k0 + 2 * kq) * DDIM + n];
                bPa[i] = base[0]; bPb[i] = base[DDIM];
            }
        }
        uint32_t ah[4][4], al[4][4], bh[3][2], bl[3][2];
        #pragma unroll
        for (int ti = 0; ti < 4; ti++) {
            int row = wm * 64 + ti * 16 + r;
            ah[ti][0] = sAh[kp][row];     ah[ti][1] = sAh[kp][row + 8];
            ah[ti][2] = sAh[kp + 4][row]; ah[ti][3] = sAh[kp + 4][row + 8];
            al[ti][0] = sAl[kp][row];     al[ti][1] = sAl[kp][row + 8];
            al[ti][2] = sAl[kp + 4][row]; al[ti][3] = sAl[kp + 4][row + 8];
        }
        #pragma unroll
        for (int tj = 0; tj < 3; tj++) {
            int col = wn * 24 + tj * 8 + r;
            bh[tj][0] = sBh[kp][col]; bh[tj][1] = sBh[kp + 4][col];
            bl[tj][0] = sBl[kp][col]; bl[tj][1] = sBl[kp + 4][col];
        }
        #pragma unroll
        for (int ti = 0; ti < 4; ti++)
            #pragma unroll
            for (int tj = 0; tj < 3; tj++) {
                mma16816(c[ti][tj], ah[ti], bh[tj]);
                mma16816(c[ti][tj], ah[ti], bl[tj]);
                mma16816(c[ti][tj], al[ti], bh[tj]);
            }
        __syncthreads();
    }

    #pragma unroll
    for (int ti = 0; ti < 4; ti++) {
        int row = m0 + wm * 64 + ti * 16 + r;
        float* oA = o + (size_t)(b * SS + row) * DDIM + h * DKK;
        float* oB = o + (size_t)(b * SS + row + 8) * DDIM + h * DKK;
        #pragma unroll
        for (int tj = 0; tj < 3; tj++) {
            int gc = wn * 24 + tj * 8 + 2 * kp;
            *(float2*)&oA[gc] = make_float2(c[ti][tj][0], c[ti][tj][1]);
            *(float2*)&oB[gc] = make_float2(c[ti][tj][2], c[ti][tj][3]);
        }
    }
}

// ---------------- fused residual + LayerNorm (optionally writes packed) ------
template<bool PACK>
__global__ void add_ln_k(const float* __restrict__ o, const float* __restrict__ x,
                         const float* __restrict__ g, const float* __restrict__ bta,
                         float* __restrict__ out,
                         uint32_t* __restrict__ oh, uint32_t* __restrict__ ol)
{
    __shared__ float red[256];
    const int row = blockIdx.x;
    const int tid = threadIdx.x;
    const float* op = o + (size_t)row * DDIM;
    const float* xp = x + (size_t)row * DDIM;
    const bool has2 = tid < 128;                 // pairs: tid and tid+256 (<384)
    float2 v0, v1 = make_float2(0.f, 0.f);
    {
        float2 a = *(const float2*)&op[2 * tid];
        float2 b = *(const float2*)&xp[2 * tid];
        v0 = make_float2(a.x + b.x, a.y + b.y);
    }
    if (has2) {
        float2 a = *(const float2*)&op[512 + 2 * tid];
        float2 b = *(const float2*)&xp[512 + 2 * tid];
        v1 = make_float2(a.x + b.x, a.y + b.y);
    }
    float lsum = v0.x + v0.y + v1.x + v1.y;
    red[tid] = lsum; __syncthreads();
    for (int st = 128; st > 0; st >>= 1) {
        if (tid < st) red[tid] += red[tid + st];
        __syncthreads();
    }
    float mean = red[0] * (1.0f / 768.0f);
    __syncthreads();
    float d0 = v0.x - mean, d1 = v0.y - mean;
    float lsq = d0 * d0 + d1 * d1;
    if (has2) { float d2 = v1.x - mean, d3 = v1.y - mean; lsq += d2 * d2 + d3 * d3; }
    red[tid] = lsq; __syncthreads();
    for (int st = 128; st > 0; st >>= 1) {
        if (tid < st) red[tid] += red[tid + st];
        __syncthreads();
    }
    float inv = rsqrtf(red[0] * (1.0f / 768.0f) + 1e-5f);

    {
        int c0 = 2 * tid;
        float y0 = (v0.x - mean) * inv * g[c0] + bta[c0];
        float y1 = (v0.y - mean) * inv * g[c0 + 1] + bta[c0 + 1];
        *(float2*)&out[(size_t)row * DDIM + c0] = make_float2(y0, y1);
        if (PACK) {
            uint32_t ph, pl; split2(y0, y1, ph, pl);
            oh[(size_t)row * DP + tid] = ph; ol[(size_t)row * DP + tid] = pl;
        }
    }
    if (has2) {
        int c0 = 512 + 2 * tid;
        float y0 = (v1.x - mean) * inv * g[c0] + bta[c0];
        float y1 = (v1.y - mean) * inv * g[c0 + 1] + bta[c0 + 1];
        *(float2*)&out[(size_t)row * DDIM + c0] = make_float2(y0, y1);
        if (PACK) {
            uint32_t ph, pl; split2(y0, y1, ph, pl);
            oh[(size_t)row * DP + 256 + tid] = ph; ol[(size_t)row * DP + 256 + tid] = pl;
        }
    }
}

// ---------------- launch -----------------------------------------------------
extern "C" void kernel_launch(void* const* d_in, const int* in_sizes, int n_in,
                              void* d_out, int out_size)
{
    const float* x     = (const float*)d_in[0];
    const void*  amask = d_in[1];
    const float* a1_Wq = (const float*)d_in[2],  *a1_bq = (const float*)d_in[3];
    const float* a1_Wv = (const float*)d_in[4],  *a1_bv = (const float*)d_in[5];
    const float* a1_g  = (const float*)d_in[6],  *a1_b  = (const float*)d_in[7];
    const float* a2_Wq = (const float*)d_in[8],  *a2_bq = (const float*)d_in[9];
    const float* a2_Wv = (const float*)d_in[10], *a2_bv = (const float*)d_in[11];
    const float* a2_g  = (const float*)d_in[12], *a2_b  = (const float*)d_in[13];
    const float* f_W1  = (const float*)d_in[14], *f_b1  = (const float*)d_in[15];
    const float* f_W2  = (const float*)d_in[16], *f_b2  = (const float*)d_in[17];
    const float* f_g   = (const float*)d_in[18], *f_b   = (const float*)d_in[19];
    float* out = (float*)d_out;

    float *p_w, *p_cm, *p_ci, *p_kv, *p_t0, *p_x1, *p_x2;
    cudaGetSymbolAddress((void**)&p_w,  g_w);
    cudaGetSymbolAddress((void**)&p_cm, g_cm);
    cudaGetSymbolAddress((void**)&p_ci, g_ci);
    cudaGetSymbolAddress((void**)&p_kv, g_kv);
    cudaGetSymbolAddress((void**)&p_t0, g_t0);
    cudaGetSymbolAddress((void**)&p_x1, g_x1);
    cudaGetSymbolAddress((void**)&p_x2, g_x2);

    uint32_t *xh,*xl,*qh,*ql,*kvh,*kvl,*x1h,*x1l,*x2h,*x2l,*hh,*hl;
    uint32_t *w1qh,*w1ql,*w1vh,*w1vl,*w2qh,*w2ql,*w2vh,*w2vl,*wf1h,*wf1l,*wf2h,*wf2l;
    cudaGetSymbolAddress((void**)&xh,  g_xh);  cudaGetSymbolAddress((void**)&xl,  g_xl);
    cudaGetSymbolAddress((void**)&qh,  g_qh);  cudaGetSymbolAddress((void**)&ql,  g_ql);
    cudaGetSymbolAddress((void**)&kvh, g_kvh); cudaGetSymbolAddress((void**)&kvl, g_kvl);
    cudaGetSymbolAddress((void**)&x1h, g_x1h); cudaGetSymbolAddress((void**)&x1l, g_x1l);
    cudaGetSymbolAddress((void**)&x2h, g_x2h); cudaGetSymbolAddress((void**)&x2l, g_x2l);
    cudaGetSymbolAddress((void**)&hh,  g_hh);  cudaGetSymbolAddress((void**)&hl,  g_hl);
    cudaGetSymbolAddress((void**)&w1qh, g_w1qh); cudaGetSymbolAddress((void**)&w1ql, g_w1ql);
    cudaGetSymbolAddress((void**)&w1vh, g_w1vh); cudaGetSymbolAddress((void**)&w1vl, g_w1vl);
    cudaGetSymbolAddress((void**)&w2qh, g_w2qh); cudaGetSymbolAddress((void**)&w2ql, g_w2ql);
    cudaGetSymbolAddress((void**)&w2vh, g_w2vh); cudaGetSymbolAddress((void**)&w2vl, g_w2vl);
    cudaGetSymbolAddress((void**)&wf1h, g_wf1h); cudaGetSymbolAddress((void**)&wf1l, g_wf1l);
    cudaGetSymbolAddress((void**)&wf2h, g_wf2h); cudaGetSymbolAddress((void**)&wf2l, g_wf2l);

    probe_mask_k<<<1, 256>>>((const unsigned char*)amask);

    // one-time operand splits
    split_rows_k<<<(MROWS * DP + 255) / 256, 256>>>(x, xh, xl, MROWS * DP);
    split_cols_k<<<(DP * DDIM + 255) / 256, 256>>>(a1_Wq, w1qh, w1ql, DDIM, DP * DDIM);
    split_cols_k<<<(DP * DDIM + 255) / 256, 256>>>(a1_Wv, w1vh, w1vl, DDIM, DP * DDIM);
    split_cols_k<<<(DP * DDIM + 255) / 256, 256>>>(a2_Wq, w2qh, w2ql, DDIM, DP * DDIM);
    split_cols_k<<<(DP * DDIM + 255) / 256, 256>>>(a2_Wv, w2vh, w2vl, DDIM, DP * DDIM);
    split_cols_k<<<(DP * FFD  + 255) / 256, 256>>>(f_W1, wf1h, wf1l, FFD,  DP * FFD);
    split_cols_k<<<(FP * DDIM + 255) / 256, 256>>>(f_W2, wf2h, wf2l, DDIM, FP * DDIM);

    const dim3 gProj(6, 64);
    const dim3 gScore(8, 8, 64);
    const dim3 gSoft(4, 64);
    const dim3 gAO(8, 64);
    const dim3 gF1(8, 64);

    // ---- MHA layer 1 ----
    gemm_tc<false, false, true><<<gProj, 256>>>(xh, xl, DP, w1qh, w1ql, DDIM, a1_bq,
                                                (float*)nullptr, qh, ql, DDIM, DDIM);
    gemm_tc<false, true,  true><<<gProj, 256>>>(xh, xl, DP, w1vh, w1vl, DDIM, a1_bv,
                                                p_kv, kvh, kvl, DDIM, DDIM);
    attn_scores_tc<<<gScore, 256>>>(qh, ql, kvh, kvl, amask, p_w);
    col_softmax_k<<<gSoft, 256>>>(p_w, p_cm, p_ci);
    attn_out_tc<<<gAO, 256>>>(p_w, p_kv, p_cm, p_ci, p_t0);
    add_ln_k<true><<<MROWS, 256>>>(p_t0, x, a1_g, a1_b, p_x1, x1h, x1l);

    // ---- MHA layer 2 ----
    gemm_tc<false, false, true><<<gProj, 256>>>(x1h, x1l, DP, w2qh, w2ql, DDIM, a2_bq,
                                                (float*)nullptr, qh, ql, DDIM, DDIM);
    gemm_tc<false, true,  true><<<gProj, 256>>>(x1h, x1l, DP, w2vh, w2vl, DDIM, a2_bv,
                                                p_kv, kvh, kvl, DDIM, DDIM);
    attn_scores_tc<<<gScore, 256>>>(qh, ql, kvh, kvl, amask, p_w);
    col_softmax_k<<<gSoft, 256>>>(p_w, p_cm, p_ci);
    attn_out_tc<<<gAO, 256>>>(p_w, p_kv, p_cm, p_ci, p_t0);
    add_ln_k<true><<<MROWS, 256>>>(p_t0, p_x1, a2_g, a2_b, p_x2, x2h, x2l);

    // ---- FFN ----
    gemm_tc<true,  false, true><<<gF1,   256>>>(x2h, x2l, DP, wf1h, wf1l, FFD, f_b1,
                                                (float*)nullptr, hh, hl, FFD, DDIM);
    gemm_tc<false, true, false><<<gProj, 256>>>(hh, hl, FP, wf2h, wf2l, DDIM, f_b2,
                                                p_t0, (uint32_t*)nullptr, (uint32_t*)nullptr,
                                                DDIM, FFD);
    add_ln_k<false><<<MROWS, 256>>>(p_t0, p_x2, f_g, f_b, out,
                                    (uint32_t*)nullptr, (uint32_t*)nullptr);
}

// round 15
// speedup vs baseline: 2.0932x; 1.0110x over previous
#include <cuda_runtime.h>
#include <cuda_bf16.h>
#include <cstdint>
#include <stdint.h>
#include <math.h>

#define BB   8
#define SS   1024
#define DDIM 768
#define HH   8
#define DKK  96
#define FFD  1024
#define BHN  (BB*HH)    // 64
#define MROWS (BB*SS)   // 8192
#define DP   (DDIM/2)   // 384 pairs
#define FP   (FFD/2)    // 512 pairs

// ---------------- scratch (device globals: allocation-free rule) ------------
__device__ float g_w [BHN*SS*SS];      // 256 MB score tensor (lower-tri only valid)
__device__ float g_cm[BHN*SS];
__device__ float g_ci[BHN*SS];
__device__ float g_kv[MROWS*DDIM];     // f32 kv (pack_v source)
__device__ float g_t0[MROWS*DDIM];
__device__ float g_x1[MROWS*DDIM];
__device__ float g_x2[MROWS*DDIM];
__device__ int   g_mask_u8;

// packed bf16 hi/lo buffers (u32 = 2 consecutive-k elements)
__device__ uint32_t g_xh [MROWS*DP],  g_xl [MROWS*DP];
__device__ uint32_t g_qh [MROWS*DP],  g_ql [MROWS*DP];
__device__ uint32_t g_kvh[MROWS*DP],  g_kvl[MROWS*DP];
__device__ uint32_t g_x1h[MROWS*DP],  g_x1l[MROWS*DP];
__device__ uint32_t g_x2h[MROWS*DP],  g_x2l[MROWS*DP];
__device__ uint32_t g_hh [MROWS*FP],  g_hl [MROWS*FP];
__device__ uint32_t g_vph[BHN*512*DKK], g_vpl[BHN*512*DKK];   // V pairs over seq
__device__ uint32_t g_w1qh[DP*DDIM], g_w1ql[DP*DDIM];
__device__ uint32_t g_w1vh[DP*DDIM], g_w1vl[DP*DDIM];
__device__ uint32_t g_w2qh[DP*DDIM], g_w2ql[DP*DDIM];
__device__ uint32_t g_w2vh[DP*DDIM], g_w2vl[DP*DDIM];
__device__ uint32_t g_wf1h[DP*FFD],  g_wf1l[DP*FFD];
__device__ uint32_t g_wf2h[FP*DDIM], g_wf2l[FP*DDIM];

// ---------------- cp.async helpers ------------------------------------------
__device__ __forceinline__ uint32_t smem_u32(const void* p) {
    return (uint32_t)__cvta_generic_to_shared(p);
}
#define CP16(dst, src) asm volatile("cp.async.cg.shared.global [%0], [%1], 16;\n" :: "r"(dst), "l"(src))
#define CPCOMMIT()     asm volatile("cp.async.commit_group;\n")
#define CPWAIT1()      asm volatile("cp.async.wait_group 1;\n")

// ---------------- mask dtype probe -----------------------------------------
__global__ void probe_mask_k(const unsigned char* __restrict__ p) {
    __shared__ int any;
    if (threadIdx.x == 0) any = 0;
    __syncthreads();
    int local = 0;
    for (int i = threadIdx.x; i < BB*SS; i += 256)
        if ((i & 3) && p[i]) local = 1;
    if (local) atomicOr(&any, 1);
    __syncthreads();
    if (threadIdx.x == 0) g_mask_u8 = any;
}

// ---------------- bf16x3 helpers --------------------------------------------
__device__ __forceinline__ void split2(float x, float y, uint32_t& h, uint32_t& l) {
    __nv_bfloat16 xh = __float2bfloat16(x);
    __nv_bfloat16 yh = __float2bfloat16(y);
    __nv_bfloat16 xl = __float2bfloat16(x - __bfloat162float(xh));
    __nv_bfloat16 yl = __float2bfloat16(y - __bfloat162float(yh));
    h = ((uint32_t)__bfloat16_as_ushort(yh) << 16) | (uint32_t)__bfloat16_as_ushort(xh);
    l = ((uint32_t)__bfloat16_as_ushort(yl) << 16) | (uint32_t)__bfloat16_as_ushort(xl);
}

__device__ __forceinline__ void mma16816(float* c, const uint32_t* a, const uint32_t* b) {
    asm volatile(
        "mma.sync.aligned.m16n8k16.row.col.f32.bf16.bf16.f32 "
        "{%0,%1,%2,%3}, {%4,%5,%6,%7}, {%8,%9}, {%0,%1,%2,%3};\n"
        : "+f"(c[0]), "+f"(c[1]), "+f"(c[2]), "+f"(c[3])
        : "r"(a[0]), "r"(a[1]), "r"(a[2]), "r"(a[3]), "r"(b[0]), "r"(b[1]));
}

#define APAD 136
#define ASTR 12       // row-major A smem stride (12 ≡ 4 mod 32 -> conflict-free)
#define BPAD96 104

// ---------------- one-time split/pack kernels --------------------------------
__global__ void split_rows_k(const float* __restrict__ s, uint32_t* __restrict__ dh,
                             uint32_t* __restrict__ dl, int npairs) {
    int p = blockIdx.x * 256 + threadIdx.x;
    if (p >= npairs) return;
    float2 v = *(const float2*)&s[(size_t)2 * p];
    split2(v.x, v.y, dh[p], dl[p]);
}
__global__ void split_cols_k(const float* __restrict__ s, uint32_t* __restrict__ dh,
                             uint32_t* __restrict__ dl, int N, int npairs) {
    int p = blockIdx.x * 256 + threadIdx.x;
    if (p >= npairs) return;
    int kq = p / N, n = p - kq * N;
    split2(s[(size_t)(2 * kq) * N + n], s[(size_t)(2 * kq + 1) * N + n], dh[p], dl[p]);
}
// V per-head pack: pairs over sequence dim. vp[bh][kq][n], kq in [0,512), n in [0,96)
__global__ void pack_v_k(const float* __restrict__ kv,
                         uint32_t* __restrict__ vh, uint32_t* __restrict__ vl) {
    int p = blockIdx.x * 256 + threadIdx.x;
    if (p >= BHN * 512 * DKK) return;
    int n = p % DKK; int t = p / DKK; int kq = t & 511; int bh = t >> 9;
    int b = bh >> 3, h = bh & 7;
    const float* base = kv + (size_t)(b * SS + 2 * kq) * DDIM + h * DKK + n;
    split2(base[0], base[DDIM], vh[p], vl[p]);
}

// ============================================================================
// Generic GEMM (packed operands, cp.async 2-stage): C = A@B + bias (+ReLU).
// A packed [M][K/2] u32 -> smem [128][ASTR]; B packed [K/2][N] -> smem [8][136].
// Block 128x128, 8 warps, warp tile 64x32, BK=16 (8 pairs), bf16x3.
// ============================================================================
template<bool RELU, bool WF32, bool WPACK>
__global__ __launch_bounds__(256)
void gemm_tc(const uint32_t* __restrict__ Ah, const uint32_t* __restrict__ Al, int ldap,
             const uint32_t* __restrict__ Bh, const uint32_t* __restrict__ Bl, int ldb,
             const float* __restrict__ bias,
             float* __restrict__ C, uint32_t* __restrict__ Ch, uint32_t* __restrict__ Cl,
             int ldc, int K)
{
    __shared__ uint32_t sAh[2][128][ASTR], sAl[2][128][ASTR];
    __shared__ uint32_t sBh[2][8][APAD],  sBl[2][8][APAD];

    const int tid = threadIdx.x;
    const int m0 = blockIdx.y * 128, n0 = blockIdx.x * 128;
    const int lane = tid & 31, warp = tid >> 5;
    const int wm = warp >> 2, wn = warp & 3;
    const int r = lane >> 2, kp = lane & 3;

    // cp.async thread mapping
    const int arow = tid >> 1, aq = (tid & 1) * 4;   // A: 128 rows x 2 quads
    const int bkb = tid >> 5,  bn4 = (lane) * 4;     // B: 8 rows x 32 quads
    const size_t aoff = (size_t)(m0 + arow) * ldap + aq;
    const size_t boff = (size_t)bkb * ldb + n0 + bn4;

    auto load_stage = [&](int st, int kt) {
        const int kq0 = kt * 8;
        CP16(smem_u32(&sAh[st][arow][aq]), Ah + aoff + kq0);
        CP16(smem_u32(&sAl[st][arow][aq]), Al + aoff + kq0);
        CP16(smem_u32(&sBh[st][bkb][bn4]), Bh + boff + (size_t)kq0 * ldb);
        CP16(smem_u32(&sBl[st][bkb][bn4]), Bl + boff + (size_t)kq0 * ldb);
        CPCOMMIT();
    };

    float c[4][4][4];
    #pragma unroll
    for (int i = 0; i < 4; i++)
        #pragma unroll
        for (int j = 0; j < 4; j++)
            #pragma unroll
            for (int e = 0; e < 4; e++) c[i][j][e] = 0.0f;

    const int KT = K >> 4;
    load_stage(0, 0);
    load_stage(1, 1);

    for (int kt = 0; kt < KT; kt++) {
        const int st = kt & 1;
        CPWAIT1();
        __syncthreads();

        uint32_t ah[4][4], al[4][4], bh[4][2], bl[4][2];
        #pragma unroll
        for (int ti = 0; ti < 4; ti++) {
            int row = wm * 64 + ti * 16 + r;
            ah[ti][0] = sAh[st][row][kp];     ah[ti][1] = sAh[st][row + 8][kp];
            ah[ti][2] = sAh[st][row][kp + 4]; ah[ti][3] = sAh[st][row + 8][kp + 4];
            al[ti][0] = sAl[st][row][kp];     al[ti][1] = sAl[st][row + 8][kp];
            al[ti][2] = sAl[st][row][kp + 4]; al[ti][3] = sAl[st][row + 8][kp + 4];
        }
        #pragma unroll
        for (int tj = 0; tj < 4; tj++) {
            int col = wn * 32 + tj * 8 + r;
            bh[tj][0] = sBh[st][kp][col]; bh[tj][1] = sBh[st][kp + 4][col];
            bl[tj][0] = sBl[st][kp][col]; bl[tj][1] = sBl[st][kp + 4][col];
        }
        #pragma unroll
        for (int ti = 0; ti < 4; ti++)
            #pragma unroll
            for (int tj = 0; tj < 4; tj++) {
                mma16816(c[ti][tj], ah[ti], bh[tj]);
                mma16816(c[ti][tj], ah[ti], bl[tj]);
                mma16816(c[ti][tj], al[ti], bh[tj]);
            }
        __syncthreads();
        if (kt + 2 < KT) load_stage(st, kt + 2);
        else             CPCOMMIT();
    }

    #pragma unroll
    for (int ti = 0; ti < 4; ti++) {
        int row = m0 + wm * 64 + ti * 16 + r;
        #pragma unroll
        for (int tj = 0; tj < 4; tj++) {
            int gc = n0 + wn * 32 + tj * 8 + 2 * kp;
            float b0 = bias[gc], b1 = bias[gc + 1];
            float v00 = c[ti][tj][0] + b0, v01 = c[ti][tj][1] + b1;
            float v10 = c[ti][tj][2] + b0, v11 = c[ti][tj][3] + b1;
            if (RELU) {
                v00 = fmaxf(v00, 0.f); v01 = fmaxf(v01, 0.f);
                v10 = fmaxf(v10, 0.f); v11 = fmaxf(v11, 0.f);
            }
            if (WF32) {
                *(float2*)&C[(size_t)row * ldc + gc]       = make_float2(v00, v01);
                *(float2*)&C[(size_t)(row + 8) * ldc + gc] = make_float2(v10, v11);
            }
            if (WPACK) {
                int ldcp = ldc >> 1, gp = gc >> 1;
                uint32_t ph, pl;
                split2(v00, v01, ph, pl);
                Ch[(size_t)row * ldcp + gp] = ph; Cl[(size_t)row * ldcp + gp] = pl;
                split2(v10, v11, ph, pl);
                Ch[(size_t)(row + 8) * ldcp + gp] = ph; Cl[(size_t)(row + 8) * ldcp + gp] = pl;
            }
        }
    }
}

// ============================================================================
// Attention scores (cp.async 2-stage, both operands row-packed [m][ASTR]).
// Above-diagonal tiles never launched work / never written.
// ============================================================================
__global__ __launch_bounds__(256)
void attn_scores_tc(const uint32_t* __restrict__ qh, const uint32_t* __restrict__ ql,
                    const uint32_t* __restrict__ kvh, const uint32_t* __restrict__ kvl,
                    const void* __restrict__ pmask, float* __restrict__ w)
{
    const int bh = blockIdx.z, b = bh >> 3, h = bh & 7;
    const int m0 = blockIdx.y * 128;
    const int n0 = blockIdx.x * 128;
    if (n0 >= m0 + 128) return;

    __shared__ uint32_t sAh[2][128][ASTR], sAl[2][128][ASTR];
    __shared__ uint32_t sBh[2][128][ASTR], sBl[2][128][ASTR];

    const uint32_t* Aph = qh  + (size_t)b * SS * DP + h * (DKK / 2);
    const uint32_t* Apl = ql  + (size_t)b * SS * DP + h * (DKK / 2);
    const uint32_t* Bph = kvh + (size_t)b * SS * DP + h * (DKK / 2);
    const uint32_t* Bpl = kvl + (size_t)b * SS * DP + h * (DKK / 2);

    const int tid = threadIdx.x;
    const int lane = tid & 31, warp = tid >> 5;
    const int wm = warp >> 2, wn = warp & 3;
    const int r = lane >> 2, kp = lane & 3;

    const int arow = tid >> 1, aq = (tid & 1) * 4;
    const size_t aoffA = (size_t)(m0 + arow) * DP + aq;
    const size_t aoffB = (size_t)(n0 + arow) * DP + aq;

    auto load_stage = [&](int st, int kt) {
        const int kq0 = kt * 8;
        CP16(smem_u32(&sAh[st][arow][aq]), Aph + aoffA + kq0);
        CP16(smem_u32(&sAl[st][arow][aq]), Apl + aoffA + kq0);
        CP16(smem_u32(&sBh[st][arow][aq]), Bph + aoffB + kq0);
        CP16(smem_u32(&sBl[st][arow][aq]), Bpl + aoffB + kq0);
        CPCOMMIT();
    };

    float c[4][4][4];
    #pragma unroll
    for (int i = 0; i < 4; i++)
        #pragma unroll
        for (int j = 0; j < 4; j++)
            #pragma unroll
            for (int e = 0; e < 4; e++) c[i][j][e] = 0.0f;

    const int KT = DKK >> 4;   // 6
    load_stage(0, 0);
    load_stage(1, 1);

    for (int kt = 0; kt < KT; kt++) {
        const int st = kt & 1;
        CPWAIT1();
        __syncthreads();

        uint32_t ah[4][4], al[4][4], bh[4][2], bl[4][2];
        #pragma unroll
        for (int ti = 0; ti < 4; ti++) {
            int row = wm * 64 + ti * 16 + r;
            ah[ti][0] = sAh[st][row][kp];     ah[ti][1] = sAh[st][row + 8][kp];
            ah[ti][2] = sAh[st][row][kp + 4]; ah[ti][3] = sAh[st][row + 8][kp + 4];
            al[ti][0] = sAl[st][row][kp];     al[ti][1] = sAl[st][row + 8][kp];
            al[ti][2] = sAl[st][row][kp + 4]; al[ti][3] = sAl[st][row + 8][kp + 4];
        }
        #pragma unroll
        for (int tj = 0; tj < 4; tj++) {
            int col = wn * 32 + tj * 8 + r;
            bh[tj][0] = sBh[st][col][kp]; bh[tj][1] = sBh[st][col][kp + 4];
            bl[tj][0] = sBl[st][col][kp]; bl[tj][1] = sBl[st][col][kp + 4];
        }
        #pragma unroll
        for (int ti = 0; ti < 4; ti++)
            #pragma unroll
            for (int tj = 0; tj < 4; tj++) {
                mma16816(c[ti][tj], ah[ti], bh[tj]);
                mma16816(c[ti][tj], ah[ti], bl[tj]);
                mma16816(c[ti][tj], al[ti], bh[tj]);
            }
        __syncthreads();
        if (kt + 2 < KT) load_stage(st, kt + 2);
        else             CPCOMMIT();
    }

    const float scale = 0.10206207261596575f;   // 1/sqrt(96)
    const unsigned char* m8  = (const unsigned char*)pmask;
    const int*           m32 = (const int*)pmask;
    const int u8 = g_mask_u8;
    float* wo = w + (size_t)bh * SS * SS;
    #pragma unroll
    for (int ti = 0; ti < 4; ti++) {
        int qrA = m0 + wm * 64 + ti * 16 + r;
        int qrB = qrA + 8;
        int padA = u8 ? (int)m8[b * SS + qrA] : m32[b * SS + qrA];
        int padB = u8 ? (int)m8[b * SS + qrB] : m32[b * SS + qrB];
        #pragma unroll
        for (int tj = 0; tj < 4; tj++) {
            int gc = n0 + wn * 32 + tj * 8 + 2 * kp;
            float v00 = ((gc     > qrA) || padA) ? -1e9f : c[ti][tj][0] * scale;
            float v01 = ((gc + 1 > qrA) || padA) ? -1e9f : c[ti][tj][1] * scale;
            float v10 = ((gc     > qrB) || padB) ? -1e9f : c[ti][tj][2] * scale;
            float v11 = ((gc + 1 > qrB) || padB) ? -1e9f : c[ti][tj][3] * scale;
            *(float2*)&wo[(size_t)qrA * SS + gc] = make_float2(v00, v01);
            *(float2*)&wo[(size_t)qrB * SS + gc] = make_float2(v10, v11);
        }
    }
}

// ---------------- online column softmax (over q axis) with causal skip ------
__global__ void col_softmax_k(const float* __restrict__ w,
                              float* __restrict__ cm, float* __restrict__ ci)
{
    const int bh = blockIdx.y;
    const int k  = blockIdx.x * 256 + threadIdx.x;
    const int qs = k & ~127;
    const float* wc = w + (size_t)bh * SS * SS + k;
    float m = -1e30f, s = 0.0f;
    for (int q = qs; q < SS; q++) {
        float v = wc[(size_t)q * SS];
        if (v > m) { s = s * expf(m - v) + 1.0f; m = v; }
        else       { s += expf(v - m); }
    }
    s += (float)qs * expf(-1e9f - m);
    cm[bh * SS + k] = m;
    ci[bh * SS + k] = 1.0f / s;
}

// ============================================================================
// o = softmax(w) @ v. Block 128x96. A: f32 w -> exp -> split (register
// prefetched). B: pre-packed V via cp.async 2-stage. Above-diagonal k-tiles
// use the constant -1e9 (w never stored there).
// ============================================================================
__global__ __launch_bounds__(256)
void attn_out_tc(const float* __restrict__ w,
                 const uint32_t* __restrict__ vph, const uint32_t* __restrict__ vpl,
                 const float* __restrict__ cm, const float* __restrict__ ci,
                 float* __restrict__ o)
{
    __shared__ uint32_t sAh[8][APAD], sAl[8][APAD];
    __shared__ uint32_t sBh[2][8][BPAD96], sBl[2][8][BPAD96];

    const int bh = blockIdx.y, b = bh >> 3, h = bh & 7;
    const int m0 = blockIdx.x * 128;
    const float* Ap  = w + (size_t)bh * SS * SS;
    const uint32_t* Vh = vph + (size_t)bh * 512 * DKK;
    const uint32_t* Vl = vpl + (size_t)bh * 512 * DKK;
    const float* cmp = cm + bh * SS;
    const float* cip = ci + bh * SS;
    const int tid = threadIdx.x;
    const int lane = tid & 31, warp = tid >> 5;
    const int wm = warp >> 2, wn = warp & 3;
    const int r = lane >> 2, kp = lane & 3;

    // B cp.async mapping: 8 kq x 96 n = 768 words; threads 0..191 one uint4 each
    const int bword = tid * 4;
    const int bkq = bword / 96, bn = bword - bkq * 96;
    const bool bact = tid < 192;

    auto load_B = [&](int st, int kt) {
        if (bact) {
            size_t src = (size_t)(kt * 8 + bkq) * DKK + bn;
            CP16(smem_u32(&sBh[st][bkq][bn]), Vh + src);
            CP16(smem_u32(&sBl[st][bkq][bn]), Vl + src);
        }
        CPCOMMIT();
    };

    float2 aP[4];
    #pragma unroll
    for (int i = 0; i < 4; i++) {
        int p = tid + i * 256;
        int m = p >> 3, kq = p & 7;
        aP[i] = *(const float2*)&Ap[(size_t)(m0 + m) * SS + 2 * kq];
    }

    float c[4][3][4];
    #pragma unroll
    for (int i = 0; i < 4; i++)
        #pragma unroll
        for (int j = 0; j < 3; j++)
            #pragma unroll
            for (int e = 0; e < 4; e++) c[i][j][e] = 0.0f;

    const int KT = SS >> 4;   // 64
    load_B(0, 0);
    load_B(1, 1);

    for (int kt = 0; kt < KT; kt++) {
        const int st = kt & 1;
        const int kb0 = kt << 4;
        const bool above = kb0 >= m0 + 128;
        #pragma unroll
        for (int i = 0; i < 4; i++) {
            int p = tid + i * 256;
            int m = p >> 3, kq = p & 7;
            int kk = kb0 + 2 * kq;
            float rawx = above ? -1e9f : aP[i].x;
            float rawy = above ? -1e9f : aP[i].y;
            float px = expf(rawx - cmp[kk])     * cip[kk];
            float py = expf(rawy - cmp[kk + 1]) * cip[kk + 1];
            split2(px, py, sAh[kq][m], sAl[kq][m]);
        }
        CPWAIT1();
        __syncthreads();
        if (kt + 1 < KT) {
            int k0 = (kt + 1) << 4;
            if (k0 < m0 + 128) {
                #pragma unroll
                for (int i = 0; i < 4; i++) {
                    int p = tid + i * 256;
                    int m = p >> 3, kq = p & 7;
                    aP[i] = *(const float2*)&Ap[(size_t)(m0 + m) * SS + k0 + 2 * kq];
                }
            }
        }
        uint32_t ah[4][4], al[4][4], bh[3][2], bl[3][2];
        #pragma unroll
        for (int ti = 0; ti < 4; ti++) {
            int row = wm * 64 + ti * 16 + r;
            ah[ti][0] = sAh[kp][row];     ah[ti][1] = sAh[kp][row + 8];
            ah[ti][2] = sAh[kp + 4][row]; ah[ti][3] = sAh[kp + 4][row + 8];
            al[ti][0] = sAl[kp][row];     al[ti][1] = sAl[kp][row + 8];
            al[ti][2] = sAl[kp + 4][row]; al[ti][3] = sAl[kp + 4][row + 8];
        }
        #pragma unroll
        for (int tj = 0; tj < 3; tj++) {
            int col = wn * 24 + tj * 8 + r;
            bh[tj][0] = sBh[st][kp][col]; bh[tj][1] = sBh[st][kp + 4][col];
            bl[tj][0] = sBl[st][kp][col]; bl[tj][1] = sBl[st][kp + 4][col];
        }
        #pragma unroll
        for (int ti = 0; ti < 4; ti++)
            #pragma unroll
            for (int tj = 0; tj < 3; tj++) {
                mma16816(c[ti][tj], ah[ti], bh[tj]);
                mma16816(c[ti][tj], ah[ti], bl[tj]);
                mma16816(c[ti][tj], al[ti], bh[tj]);
            }
        __syncthreads();
        if (kt + 2 < KT) load_B(st, kt + 2);
        else             CPCOMMIT();
    }

    #pragma unroll
    for (int ti = 0; ti < 4; ti++) {
        int row = m0 + wm * 64 + ti * 16 + r;
        float* oA = o + (size_t)(b * SS + row) * DDIM + h * DKK;
        float* oB = o + (size_t)(b * SS + row + 8) * DDIM + h * DKK;
        #pragma unroll
        for (int tj = 0; tj < 3; tj++) {
            int gc = wn * 24 + tj * 8 + 2 * kp;
            *(float2*)&oA[gc] = make_float2(c[ti][tj][0], c[ti][tj][1]);
            *(float2*)&oB[gc] = make_float2(c[ti][tj][2], c[ti][tj][3]);
        }
    }
}

// ---------------- fused residual + LayerNorm (optionally writes packed) ------
template<bool PACK>
__global__ void add_ln_k(const float* __restrict__ o, const float* __restrict__ x,
                         const float* __restrict__ g, const float* __restrict__ bta,
                         float* __restrict__ out,
                         uint32_t* __restrict__ oh, uint32_t* __restrict__ ol)
{
    __shared__ float red[256];
    const int row = blockIdx.x;
    const int tid = threadIdx.x;
    const float* op = o + (size_t)row * DDIM;
    const float* xp = x + (size_t)row * DDIM;
    const bool has2 = tid < 128;
    float2 v0, v1 = make_float2(0.f, 0.f);
    {
        float2 a = *(const float2*)&op[2 * tid];
        float2 b = *(const float2*)&xp[2 * tid];
        v0 = make_float2(a.x + b.x, a.y + b.y);
    }
    if (has2) {
        float2 a = *(const float2*)&op[512 + 2 * tid];
        float2 b = *(const float2*)&xp[512 + 2 * tid];
        v1 = make_float2(a.x + b.x, a.y + b.y);
    }
    float lsum = v0.x + v0.y + v1.x + v1.y;
    red[tid] = lsum; __syncthreads();
    for (int st = 128; st > 0; st >>= 1) {
        if (tid < st) red[tid] += red[tid + st];
        __syncthreads();
    }
    float mean = red[0] * (1.0f / 768.0f);
    __syncthreads();
    float d0 = v0.x - mean, d1 = v0.y - mean;
    float lsq = d0 * d0 + d1 * d1;
    if (has2) { float d2 = v1.x - mean, d3 = v1.y - mean; lsq += d2 * d2 + d3 * d3; }
    red[tid] = lsq; __syncthreads();
    for (int st = 128; st > 0; st >>= 1) {
        if (tid < st) red[tid] += red[tid + st];
        __syncthreads();
    }
    float inv = rsqrtf(red[0] * (1.0f / 768.0f) + 1e-5f);

    {
        int c0 = 2 * tid;
        float y0 = (v0.x - mean) * inv * g[c0] + bta[c0];
        float y1 = (v0.y - mean) * inv * g[c0 + 1] + bta[c0 + 1];
        *(float2*)&out[(size_t)row * DDIM + c0] = make_float2(y0, y1);
        if (PACK) {
            uint32_t ph, pl; split2(y0, y1, ph, pl);
            oh[(size_t)row * DP + tid] = ph; ol[(size_t)row * DP + tid] = pl;
        }
    }
    if (has2) {
        int c0 = 512 + 2 * tid;
        float y0 = (v1.x - mean) * inv * g[c0] + bta[c0];
        float y1 = (v1.y - mean) * inv * g[c0 + 1] + bta[c0 + 1];
        *(float2*)&out[(size_t)row * DDIM + c0] = make_float2(y0, y1);
        if (PACK) {
            uint32_t ph, pl; split2(y0, y1, ph, pl);
            oh[(size_t)row * DP + 256 + tid] = ph; ol[(size_t)row * DP + 256 + tid] = pl;
        }
    }
}

// ---------------- launch -----------------------------------------------------
extern "C" void kernel_launch(void* const* d_in, const int* in_sizes, int n_in,
                              void* d_out, int out_size)
{
    const float* x     = (const float*)d_in[0];
    const void*  amask = d_in[1];
    const float* a1_Wq = (const float*)d_in[2],  *a1_bq = (const float*)d_in[3];
    const float* a1_Wv = (const float*)d_in[4],  *a1_bv = (const float*)d_in[5];
    const float* a1_g  = (const float*)d_in[6],  *a1_b  = (const float*)d_in[7];
    const float* a2_Wq = (const float*)d_in[8],  *a2_bq = (const float*)d_in[9];
    const float* a2_Wv = (const float*)d_in[10], *a2_bv = (const float*)d_in[11];
    const float* a2_g  = (const float*)d_in[12], *a2_b  = (const float*)d_in[13];
    const float* f_W1  = (const float*)d_in[14], *f_b1  = (const float*)d_in[15];
    const float* f_W2  = (const float*)d_in[16], *f_b2  = (const float*)d_in[17];
    const float* f_g   = (const float*)d_in[18], *f_b   = (const float*)d_in[19];
    float* out = (float*)d_out;

    float *p_w, *p_cm, *p_ci, *p_kv, *p_t0, *p_x1, *p_x2;
    cudaGetSymbolAddress((void**)&p_w,  g_w);
    cudaGetSymbolAddress((void**)&p_cm, g_cm);
    cudaGetSymbolAddress((void**)&p_ci, g_ci);
    cudaGetSymbolAddress((void**)&p_kv, g_kv);
    cudaGetSymbolAddress((void**)&p_t0, g_t0);
    cudaGetSymbolAddress((void**)&p_x1, g_x1);
    cudaGetSymbolAddress((void**)&p_x2, g_x2);

    uint32_t *xh,*xl,*qh,*ql,*kvh,*kvl,*x1h,*x1l,*x2h,*x2l,*hh,*hl,*vph,*vpl;
    uint32_t *w1qh,*w1ql,*w1vh,*w1vl,*w2qh,*w2ql,*w2vh,*w2vl,*wf1h,*wf1l,*wf2h,*wf2l;
    cudaGetSymbolAddress((void**)&xh,  g_xh);  cudaGetSymbolAddress((void**)&xl,  g_xl);
    cudaGetSymbolAddress((void**)&qh,  g_qh);  cudaGetSymbolAddress((void**)&ql,  g_ql);
    cudaGetSymbolAddress((void**)&kvh, g_kvh); cudaGetSymbolAddress((void**)&kvl, g_kvl);
    cudaGetSymbolAddress((void**)&x1h, g_x1h); cudaGetSymbolAddress((void**)&x1l, g_x1l);
    cudaGetSymbolAddress((void**)&x2h, g_x2h); cudaGetSymbolAddress((void**)&x2l, g_x2l);
    cudaGetSymbolAddress((void**)&hh,  g_hh);  cudaGetSymbolAddress((void**)&hl,  g_hl);
    cudaGetSymbolAddress((void**)&vph, g_vph); cudaGetSymbolAddress((void**)&vpl, g_vpl);
    cudaGetSymbolAddress((void**)&w1qh, g_w1qh); cudaGetSymbolAddress((void**)&w1ql, g_w1ql);
    cudaGetSymbolAddress((void**)&w1vh, g_w1vh); cudaGetSymbolAddress((void**)&w1vl, g_w1vl);
    cudaGetSymbolAddress((void**)&w2qh, g_w2qh); cudaGetSymbolAddress((void**)&w2ql, g_w2ql);
    cudaGetSymbolAddress((void**)&w2vh, g_w2vh); cudaGetSymbolAddress((void**)&w2vl, g_w2vl);
    cudaGetSymbolAddress((void**)&wf1h, g_wf1h); cudaGetSymbolAddress((void**)&wf1l, g_wf1l);
    cudaGetSymbolAddress((void**)&wf2h, g_wf2h); cudaGetSymbolAddress((void**)&wf2l, g_wf2l);

    probe_mask_k<<<1, 256>>>((const unsigned char*)amask);

    split_rows_k<<<(MROWS * DP + 255) / 256, 256>>>(x, xh, xl, MROWS * DP);
    split_cols_k<<<(DP * DDIM + 255) / 256, 256>>>(a1_Wq, w1qh, w1ql, DDIM, DP * DDIM);
    split_cols_k<<<(DP * DDIM + 255) / 256, 256>>>(a1_Wv, w1vh, w1vl, DDIM, DP * DDIM);
    split_cols_k<<<(DP * DDIM + 255) / 256, 256>>>(a2_Wq, w2qh, w2ql, DDIM, DP * DDIM);
    split_cols_k<<<(DP * DDIM + 255) / 256, 256>>>(a2_Wv, w2vh, w2vl, DDIM, DP * DDIM);
    split_cols_k<<<(DP * FFD  + 255) / 256, 256>>>(f_W1, wf1h, wf1l, FFD,  DP * FFD);
    split_cols_k<<<(FP * DDIM + 255) / 256, 256>>>(f_W2, wf2h, wf2l, DDIM, FP * DDIM);

    const dim3 gProj(6, 64);
    const dim3 gScore(8, 8, 64);
    const dim3 gSoft(4, 64);
    const dim3 gAO(8, 64);
    const dim3 gF1(8, 64);
    const int  gPackV = (BHN * 512 * DKK + 255) / 256;

    // ---- MHA layer 1 ----
    gemm_tc<false, false, true><<<gProj, 256>>>(xh, xl, DP, w1qh, w1ql, DDIM, a1_bq,
                                                (float*)nullptr, qh, ql, DDIM, DDIM);
    gemm_tc<false, true,  true><<<gProj, 256>>>(xh, xl, DP, w1vh, w1vl, DDIM, a1_bv,
                                                p_kv, kvh, kvl, DDIM, DDIM);
    pack_v_k<<<gPackV, 256>>>(p_kv, vph, vpl);
    attn_scores_tc<<<gScore, 256>>>(qh, ql, kvh, kvl, amask, p_w);
    col_softmax_k<<<gSoft, 256>>>(p_w, p_cm, p_ci);
    attn_out_tc<<<gAO, 256>>>(p_w, vph, vpl, p_cm, p_ci, p_t0);
    add_ln_k<true><<<MROWS, 256>>>(p_t0, x, a1_g, a1_b, p_x1, x1h, x1l);

    // ---- MHA layer 2 ----
    gemm_tc<false, false, true><<<gProj, 256>>>(x1h, x1l, DP, w2qh, w2ql, DDIM, a2_bq,
                                                (float*)nullptr, qh, ql, DDIM, DDIM);
    gemm_tc<false, true,  true><<<gProj, 256>>>(x1h, x1l, DP, w2vh, w2vl, DDIM, a2_bv,
                                                p_kv, kvh, kvl, DDIM, DDIM);
    pack_v_k<<<gPackV, 256>>>(p_kv, vph, vpl);
    attn_scores_tc<<<gScore, 256>>>(qh, ql, kvh, kvl, amask, p_w);
    col_softmax_k<<<gSoft, 256>>>(p_w, p_cm, p_ci);
    attn_out_tc<<<gAO, 256>>>(p_w, vph, vpl, p_cm, p_ci, p_t0);
    add_ln_k<true><<<MROWS, 256>>>(p_t0, p_x1, a2_g, a2_b, p_x2, x2h, x2l);

    // ---- FFN ----
    gemm_tc<true,  false, true><<<gF1,   256>>>(x2h, x2l, DP, wf1h, wf1l, FFD, f_b1,
                                                (float*)nullptr, hh, hl, FFD, DDIM);
    gemm_tc<false, true, false><<<gProj, 256>>>(hh, hl, FP, wf2h, wf2l, DDIM, f_b2,
                                                p_t0, (uint32_t*)nullptr, (uint32_t*)nullptr,
                                                DDIM, FFD);
    add_ln_k<false><<<MROWS, 256>>>(p_t0, p_x2, f_g, f_b, out,
                                    (uint32_t*)nullptr, (uint32_t*)nullptr);
}